// round 1
// baseline (speedup 1.0000x reference)
#include <cuda_runtime.h>
#include <cstdint>

#define HIDDEN 1024
#define NH 16
#define HS 64
#define BB 2
#define SS 2048
#define M_TOT (BB*SS)       /* 4096 */
#define QKV_N (3*HIDDEN)    /* 3072 */

// Scratch buffers (static device globals — no runtime allocation).
__device__ float g_qkv[(size_t)M_TOT * QKV_N];    // 48 MB
__device__ float g_attn[(size_t)M_TOT * HIDDEN];  // 16 MB

// ---------------------------------------------------------------------------
// Tiled SGEMM: C[M,N] = A[M,K] @ B[K,N] + bias[N]
// BM=BN=64, BK=16, block 16x16, 4x4 per-thread micro-tile.
// A tile stored transposed in smem for vectorized float4 reads.
// M,N,K all divide the tile sizes exactly for our shapes (no bounds checks).
// ---------------------------------------------------------------------------
__global__ __launch_bounds__(256) void sgemm_bias_kernel(
    const float* __restrict__ A, const float* __restrict__ B,
    const float* __restrict__ bias, float* __restrict__ C,
    int M, int N, int K)
{
    __shared__ float At[16][68];   // [BK][BM+4]
    __shared__ float Bs[16][64];   // [BK][BN]

    const int tx = threadIdx.x, ty = threadIdx.y;
    const int tid = ty * 16 + tx;
    const int row0 = blockIdx.y * 64;
    const int col0 = blockIdx.x * 64;

    float acc[4][4] = {};

    for (int k0 = 0; k0 < K; k0 += 16) {
        // Load A tile 64x16 (one float4 per thread), store transposed.
        {
            const int r = tid >> 2;            // 0..63
            const int v = (tid & 3) * 4;       // 0,4,8,12
            float4 a = *(const float4*)&A[(size_t)(row0 + r) * K + k0 + v];
            At[v + 0][r] = a.x; At[v + 1][r] = a.y;
            At[v + 2][r] = a.z; At[v + 3][r] = a.w;
        }
        // Load B tile 16x64 (one float4 per thread).
        {
            const int r = tid >> 4;            // 0..15
            const int v = (tid & 15) * 4;      // 0..60
            *(float4*)&Bs[r][v] = *(const float4*)&B[(size_t)(k0 + r) * N + col0 + v];
        }
        __syncthreads();

        #pragma unroll
        for (int k = 0; k < 16; k++) {
            float4 a4 = *(const float4*)&At[k][ty * 4];
            float4 b4 = *(const float4*)&Bs[k][tx * 4];
            float av[4] = {a4.x, a4.y, a4.z, a4.w};
            float bv[4] = {b4.x, b4.y, b4.z, b4.w};
            #pragma unroll
            for (int i = 0; i < 4; i++)
                #pragma unroll
                for (int j = 0; j < 4; j++)
                    acc[i][j] += av[i] * bv[j];
        }
        __syncthreads();
    }

    #pragma unroll
    for (int i = 0; i < 4; i++) {
        const int r = row0 + ty * 4 + i;
        #pragma unroll
        for (int j = 0; j < 4; j++) {
            const int c = col0 + tx * 4 + j;
            C[(size_t)r * N + c] = acc[i][j] + bias[c];
        }
    }
}

// ---------------------------------------------------------------------------
// Flash attention (fp32, streaming softmax).
// grid.x = B*NH, grid.y = S/64. Block 16x16.
// Each block: 64 query rows of one (b,h); streams over key tiles of 64.
// Thread (tx,ty) owns S-tile rows ty*4+i, cols tx*4+j; O cols are d = tx*4+j.
// Row stats reduced across the 16 threads of a half-warp via shfl.
// ---------------------------------------------------------------------------
__global__ __launch_bounds__(256) void flash_attn_kernel(
    const float* __restrict__ qkv, float* __restrict__ attn)
{
    const int bh = blockIdx.x;
    const int b = bh / NH, h = bh % NH;
    const int q0 = blockIdx.y * 64;
    const int tx = threadIdx.x, ty = threadIdx.y;
    const int tid = ty * 16 + tx;

    __shared__ float Qt[64][68];   // [d][row], Q pre-scaled
    __shared__ float Kt[64][68];   // [d][col]
    __shared__ float Vs[64][64];   // [k][d]
    __shared__ float Pt[64][68];   // [k][row]

    const float scale = 0.125f;    // 1/sqrt(64)
    const float* qbase = qkv + (size_t)b * SS * QKV_N + h * HS;
    const float* kbase = qbase + HIDDEN;
    const float* vbase = qbase + 2 * HIDDEN;

    // Load Q tile (64 rows x 64 d), scaled, transposed into Qt.
    #pragma unroll
    for (int it = 0; it < 4; it++) {
        const int idx = tid + 256 * it;   // 0..1023
        const int r = idx >> 4;           // 0..63
        const int dv = (idx & 15) * 4;    // 0..60
        float4 q4 = *(const float4*)&qbase[(size_t)(q0 + r) * QKV_N + dv];
        Qt[dv + 0][r] = q4.x * scale; Qt[dv + 1][r] = q4.y * scale;
        Qt[dv + 2][r] = q4.z * scale; Qt[dv + 3][r] = q4.w * scale;
    }

    float acc[4][4] = {};
    float m[4], l[4];
    #pragma unroll
    for (int i = 0; i < 4; i++) { m[i] = -1e30f; l[i] = 0.f; }

    for (int k0 = 0; k0 < SS; k0 += 64) {
        // Load K tile (transposed) and V tile.
        #pragma unroll
        for (int it = 0; it < 4; it++) {
            const int idx = tid + 256 * it;
            const int r = idx >> 4;
            const int dv = (idx & 15) * 4;
            float4 k4 = *(const float4*)&kbase[(size_t)(k0 + r) * QKV_N + dv];
            Kt[dv + 0][r] = k4.x; Kt[dv + 1][r] = k4.y;
            Kt[dv + 2][r] = k4.z; Kt[dv + 3][r] = k4.w;
            float4 v4 = *(const float4*)&vbase[(size_t)(k0 + r) * QKV_N + dv];
            *(float4*)&Vs[r][dv] = v4;
        }
        __syncthreads();

        // S tile = (Q*scale) @ K^T : 4x4 per thread.
        float s[4][4] = {};
        #pragma unroll
        for (int d = 0; d < 64; d++) {
            float4 qa = *(const float4*)&Qt[d][ty * 4];
            float4 kb = *(const float4*)&Kt[d][tx * 4];
            float qv[4] = {qa.x, qa.y, qa.z, qa.w};
            float kv[4] = {kb.x, kb.y, kb.z, kb.w};
            #pragma unroll
            for (int i = 0; i < 4; i++)
                #pragma unroll
                for (int j = 0; j < 4; j++)
                    s[i][j] += qv[i] * kv[j];
        }

        // Online softmax (per-row across the 16 tx threads: half-warp shfl).
        #pragma unroll
        for (int i = 0; i < 4; i++) {
            float rm = fmaxf(fmaxf(s[i][0], s[i][1]), fmaxf(s[i][2], s[i][3]));
            #pragma unroll
            for (int off = 8; off; off >>= 1)
                rm = fmaxf(rm, __shfl_xor_sync(0xffffffffu, rm, off));
            const float mn = fmaxf(m[i], rm);
            const float alpha = __expf(m[i] - mn);
            m[i] = mn;
            float rs = 0.f;
            #pragma unroll
            for (int j = 0; j < 4; j++) { s[i][j] = __expf(s[i][j] - mn); rs += s[i][j]; }
            #pragma unroll
            for (int off = 8; off; off >>= 1)
                rs += __shfl_xor_sync(0xffffffffu, rs, off);
            l[i] = l[i] * alpha + rs;
            #pragma unroll
            for (int j = 0; j < 4; j++) acc[i][j] *= alpha;
        }

        // Publish P transposed for the PV GEMM.
        #pragma unroll
        for (int i = 0; i < 4; i++)
            #pragma unroll
            for (int j = 0; j < 4; j++)
                Pt[tx * 4 + j][ty * 4 + i] = s[i][j];
        __syncthreads();

        // O += P @ V
        #pragma unroll
        for (int kk = 0; kk < 64; kk++) {
            float4 pa = *(const float4*)&Pt[kk][ty * 4];
            float4 vb = *(const float4*)&Vs[kk][tx * 4];
            float pv[4] = {pa.x, pa.y, pa.z, pa.w};
            float vv[4] = {vb.x, vb.y, vb.z, vb.w};
            #pragma unroll
            for (int i = 0; i < 4; i++)
                #pragma unroll
                for (int j = 0; j < 4; j++)
                    acc[i][j] += pv[i] * vv[j];
        }
        __syncthreads();   // protect Kt/Vs/Pt before next tile load
    }

    // Normalize and write to attn buffer [b, s, h*HS + d].
    #pragma unroll
    for (int i = 0; i < 4; i++) {
        const int r = q0 + ty * 4 + i;
        const float inv = 1.f / l[i];
        #pragma unroll
        for (int j = 0; j < 4; j++) {
            attn[((size_t)b * SS + r) * HIDDEN + h * HS + tx * 4 + j] = acc[i][j] * inv;
        }
    }
}

// ---------------------------------------------------------------------------
extern "C" void kernel_launch(void* const* d_in, const int* in_sizes, int n_in,
                              void* d_out, int out_size)
{
    (void)in_sizes; (void)n_in; (void)out_size;
    const float* x    = (const float*)d_in[0];
    const float* Wqkv = (const float*)d_in[1];
    const float* bqkv = (const float*)d_in[2];
    const float* Wo   = (const float*)d_in[3];
    const float* bo   = (const float*)d_in[4];
    float* out = (float*)d_out;

    float* qkv_buf = nullptr;
    float* attn_buf = nullptr;
    cudaGetSymbolAddress((void**)&qkv_buf, g_qkv);
    cudaGetSymbolAddress((void**)&attn_buf, g_attn);

    dim3 blk(16, 16);

    // 1) QKV projection: [4096,1024] @ [1024,3072] + bqkv
    {
        dim3 grid(QKV_N / 64, M_TOT / 64);   // (48, 64)
        sgemm_bias_kernel<<<grid, blk>>>(x, Wqkv, bqkv, qkv_buf,
                                         M_TOT, QKV_N, HIDDEN);
    }
    // 2) Flash attention
    {
        dim3 grid(BB * NH, SS / 64);         // (32, 32)
        flash_attn_kernel<<<grid, blk>>>(qkv_buf, attn_buf);
    }
    // 3) Output projection: [4096,1024] @ [1024,1024] + bo
    {
        dim3 grid(HIDDEN / 64, M_TOT / 64);  // (16, 64)
        sgemm_bias_kernel<<<grid, blk>>>(attn_buf, Wo, bo, out,
                                         M_TOT, HIDDEN, HIDDEN);
    }
}

// round 7
// speedup vs baseline: 2.4373x; 2.4373x over previous
#include <cuda_runtime.h>
#include <cstdint>

#define HIDDEN 1024
#define NH 16
#define HS 64
#define BB 2
#define SS 2048
#define M_TOT (BB*SS)       /* 4096 */
#define QKV_N (3*HIDDEN)    /* 3072 */

// Scratch buffers (static device globals — no runtime allocation).
__device__ float g_qkv[(size_t)M_TOT * QKV_N];    // 48 MB
__device__ float g_attn[(size_t)M_TOT * HIDDEN];  // 16 MB

// ---------------------------------------------------------------------------
// Helpers
// ---------------------------------------------------------------------------
__device__ __forceinline__ float f2tf(float x) {
    // round-to-nearest tf32, result kept in a 32-bit reg (low mantissa zeroed)
    unsigned r;
    asm("cvt.rna.tf32.f32 %0, %1;" : "=r"(r) : "f"(x));
    return __uint_as_float(r);
}

__device__ __forceinline__ void mma_tf32(float* c, const unsigned* a, const unsigned* b) {
    asm volatile(
        "mma.sync.aligned.m16n8k8.row.col.f32.tf32.tf32.f32 "
        "{%0,%1,%2,%3}, {%4,%5,%6,%7}, {%8,%9}, {%0,%1,%2,%3};\n"
        : "+f"(c[0]), "+f"(c[1]), "+f"(c[2]), "+f"(c[3])
        : "r"(a[0]), "r"(a[1]), "r"(a[2]), "r"(a[3]),
          "r"(b[0]), "r"(b[1]));
}

// ---------------------------------------------------------------------------
// TF32 tensor-core GEMM: C[M,N] = A[M,K] @ B[K,N] + bias[N]
// BM=BN=128, BK=32. 256 threads = 8 warps in 4(m) x 2(n); warp tile 32x64.
// smem As[k][m], Bs[k][n] pitch 136 (= 8 mod 32 banks -> conflict-free frags).
// ---------------------------------------------------------------------------
__global__ __launch_bounds__(256) void gemm_tf32_kernel(
    const float* __restrict__ A, const float* __restrict__ B,
    const float* __restrict__ bias, float* __restrict__ C,
    int M, int N, int K)
{
    __shared__ float As[32][136];
    __shared__ float Bs[32][136];

    const int tid  = threadIdx.x;
    const int lane = tid & 31;
    const int wid  = tid >> 5;
    const int g = lane >> 2;          // 0..7
    const int t = lane & 3;           // 0..3
    const int wm = (wid & 3) * 32;    // warp m offset in tile
    const int wn = (wid >> 2) * 64;   // warp n offset in tile
    const int row0 = blockIdx.y * 128;
    const int col0 = blockIdx.x * 128;

    float c[2][8][4] = {};

    // staging coords
    const int ar = tid >> 1;            // A row 0..127
    const int ac = (tid & 1) * 16;      // A col base (0 or 16)

    float4 pa[4], pb[4];

    // prologue load (k0 = 0)
    #pragma unroll
    for (int i = 0; i < 4; i++)
        pa[i] = *(const float4*)&A[(size_t)(row0 + ar) * K + ac + 4 * i];
    #pragma unroll
    for (int i = 0; i < 4; i++) {
        const int e = tid + 256 * i;
        pb[i] = *(const float4*)&B[(size_t)(e >> 5) * N + col0 + (e & 31) * 4];
    }

    const int NIT = K / 32;
    for (int it = 0; it < NIT; it++) {
        // store staged tile to smem (tf32-rounded)
        #pragma unroll
        for (int i = 0; i < 4; i++) {
            As[ac + 4*i + 0][ar] = f2tf(pa[i].x);
            As[ac + 4*i + 1][ar] = f2tf(pa[i].y);
            As[ac + 4*i + 2][ar] = f2tf(pa[i].z);
            As[ac + 4*i + 3][ar] = f2tf(pa[i].w);
        }
        #pragma unroll
        for (int i = 0; i < 4; i++) {
            const int e = tid + 256 * i;
            float4 v = pb[i];
            v.x = f2tf(v.x); v.y = f2tf(v.y); v.z = f2tf(v.z); v.w = f2tf(v.w);
            *(float4*)&Bs[e >> 5][(e & 31) * 4] = v;
        }
        __syncthreads();

        // prefetch next tile
        if (it + 1 < NIT) {
            const int k0 = (it + 1) * 32;
            #pragma unroll
            for (int i = 0; i < 4; i++)
                pa[i] = *(const float4*)&A[(size_t)(row0 + ar) * K + k0 + ac + 4 * i];
            #pragma unroll
            for (int i = 0; i < 4; i++) {
                const int e = tid + 256 * i;
                pb[i] = *(const float4*)&B[(size_t)(k0 + (e >> 5)) * N + col0 + (e & 31) * 4];
            }
        }

        // compute 4 k-steps of 8
        #pragma unroll
        for (int ks = 0; ks < 4; ks++) {
            const int kb = ks * 8;
            unsigned a[2][4], b[8][2];
            #pragma unroll
            for (int mt = 0; mt < 2; mt++) {
                const int mb = wm + mt * 16;
                a[mt][0] = __float_as_uint(As[kb + t    ][mb + g    ]);
                a[mt][1] = __float_as_uint(As[kb + t    ][mb + g + 8]);
                a[mt][2] = __float_as_uint(As[kb + t + 4][mb + g    ]);
                a[mt][3] = __float_as_uint(As[kb + t + 4][mb + g + 8]);
            }
            #pragma unroll
            for (int nt = 0; nt < 8; nt++) {
                b[nt][0] = __float_as_uint(Bs[kb + t    ][wn + nt * 8 + g]);
                b[nt][1] = __float_as_uint(Bs[kb + t + 4][wn + nt * 8 + g]);
            }
            #pragma unroll
            for (int mt = 0; mt < 2; mt++)
                #pragma unroll
                for (int nt = 0; nt < 8; nt++)
                    mma_tf32(c[mt][nt], a[mt], b[nt]);
        }
        __syncthreads();
    }

    // epilogue: bias + store (float2)
    #pragma unroll
    for (int mt = 0; mt < 2; mt++) {
        const int r = row0 + wm + mt * 16 + g;
        #pragma unroll
        for (int nt = 0; nt < 8; nt++) {
            const int cn = col0 + wn + nt * 8 + t * 2;
            const float b0 = bias[cn], b1 = bias[cn + 1];
            float2 v0 = make_float2(c[mt][nt][0] + b0, c[mt][nt][1] + b1);
            float2 v1 = make_float2(c[mt][nt][2] + b0, c[mt][nt][3] + b1);
            *(float2*)&C[(size_t)r * N + cn]       = v0;
            *(float2*)&C[(size_t)(r + 8) * N + cn] = v1;
        }
    }
}

// ---------------------------------------------------------------------------
// Flash attention, tf32 tensor cores.
// grid = (B*NH, SS/128), 256 threads = 8 warps; warp w owns q rows 16w..16w+15
// of the 128-row Q tile. Streams 64-key tiles; S and PV both via mma.
// smem (dynamic, 104 KB):
//   Qs[128][68]  (q,d)   pre-scaled; pitch 68 -> A-frag conflict-free
//   Ps[128][68]  (q,key)
//   Kt[64][72]   (d,key) pitch 72 -> B-frag conflict-free
//   Vs[64][72]   (key,d)
// ---------------------------------------------------------------------------
#define QP 68
#define KP 72

__global__ __launch_bounds__(256) void flash_tf32_kernel(
    const float* __restrict__ qkv, float* __restrict__ attn)
{
    extern __shared__ float sm[];
    float* Qs = sm;                      // 128*68
    float* Ps = Qs + 128 * QP;           // 128*68
    float* Kt = Ps + 128 * QP;           // 64*72
    float* Vs = Kt + 64 * KP;            // 64*72

    const int bh = blockIdx.x;
    const int b = bh / NH, h = bh % NH;
    const int q0 = blockIdx.y * 128;
    const int tid = threadIdx.x;
    const int lane = tid & 31;
    const int wid = tid >> 5;
    const int g = lane >> 2, t = lane & 3;
    const int m0 = wid * 16;             // warp's q-row offset in tile

    const float scale = 0.125f;
    const float* qbase = qkv + (size_t)b * SS * QKV_N + h * HS;
    const float* kbase = qbase + HIDDEN;
    const float* vbase = qbase + 2 * HIDDEN;

    // Load Q tile (128 x 64), scale + tf32 round.
    #pragma unroll
    for (int i = 0; i < 8; i++) {
        const int e = tid + 256 * i;     // 0..2047
        const int r = e >> 4;            // 0..127
        const int dc = (e & 15) * 4;
        float4 q4 = *(const float4*)&qbase[(size_t)(q0 + r) * QKV_N + dc];
        q4.x = f2tf(q4.x * scale); q4.y = f2tf(q4.y * scale);
        q4.z = f2tf(q4.z * scale); q4.w = f2tf(q4.w * scale);
        *(float4*)&Qs[r * QP + dc] = q4;
    }

    float o[8][4] = {};
    float mrow0 = -1e30f, mrow1 = -1e30f, l0 = 0.f, l1 = 0.f;

    for (int k0 = 0; k0 < SS; k0 += 64) {
        __syncthreads();   // previous iter's consumers done with Kt/Vs
        // Load K tile transposed + V tile (64 x 64 each).
        #pragma unroll
        for (int i = 0; i < 4; i++) {
            const int e = tid + 256 * i;     // 0..1023
            const int key = e >> 4;          // 0..63
            const int dc = (e & 15) * 4;
            float4 k4 = *(const float4*)&kbase[(size_t)(k0 + key) * QKV_N + dc];
            Kt[(dc + 0) * KP + key] = f2tf(k4.x);
            Kt[(dc + 1) * KP + key] = f2tf(k4.y);
            Kt[(dc + 2) * KP + key] = f2tf(k4.z);
            Kt[(dc + 3) * KP + key] = f2tf(k4.w);
            float4 v4 = *(const float4*)&vbase[(size_t)(k0 + key) * QKV_N + dc];
            v4.x = f2tf(v4.x); v4.y = f2tf(v4.y); v4.z = f2tf(v4.z); v4.w = f2tf(v4.w);
            *(float4*)&Vs[key * KP + dc] = v4;
        }
        __syncthreads();

        // ---- S = Q @ K^T  (m16 x n64, k=64) ----
        float s[8][4] = {};
        #pragma unroll
        for (int ks = 0; ks < 8; ks++) {
            const int kb = ks * 8;
            unsigned a[4], bfr[8][2];
            a[0] = __float_as_uint(Qs[(m0 + g    ) * QP + kb + t    ]);
            a[1] = __float_as_uint(Qs[(m0 + g + 8) * QP + kb + t    ]);
            a[2] = __float_as_uint(Qs[(m0 + g    ) * QP + kb + t + 4]);
            a[3] = __float_as_uint(Qs[(m0 + g + 8) * QP + kb + t + 4]);
            #pragma unroll
            for (int nt = 0; nt < 8; nt++) {
                bfr[nt][0] = __float_as_uint(Kt[(kb + t    ) * KP + nt * 8 + g]);
                bfr[nt][1] = __float_as_uint(Kt[(kb + t + 4) * KP + nt * 8 + g]);
            }
            #pragma unroll
            for (int nt = 0; nt < 8; nt++)
                mma_tf32(s[nt], a, bfr[nt]);
        }

        // ---- online softmax (rows g and g+8 of this warp) ----
        float mx0 = -1e30f, mx1 = -1e30f;
        #pragma unroll
        for (int nt = 0; nt < 8; nt++) {
            mx0 = fmaxf(mx0, fmaxf(s[nt][0], s[nt][1]));
            mx1 = fmaxf(mx1, fmaxf(s[nt][2], s[nt][3]));
        }
        mx0 = fmaxf(mx0, __shfl_xor_sync(0xffffffffu, mx0, 1));
        mx0 = fmaxf(mx0, __shfl_xor_sync(0xffffffffu, mx0, 2));
        mx1 = fmaxf(mx1, __shfl_xor_sync(0xffffffffu, mx1, 1));
        mx1 = fmaxf(mx1, __shfl_xor_sync(0xffffffffu, mx1, 2));

        const float mn0 = fmaxf(mrow0, mx0);
        const float mn1 = fmaxf(mrow1, mx1);
        const float al0 = __expf(mrow0 - mn0);
        const float al1 = __expf(mrow1 - mn1);
        mrow0 = mn0; mrow1 = mn1;

        float sum0 = 0.f, sum1 = 0.f;
        #pragma unroll
        for (int nt = 0; nt < 8; nt++) {
            s[nt][0] = __expf(s[nt][0] - mn0); sum0 += s[nt][0];
            s[nt][1] = __expf(s[nt][1] - mn0); sum0 += s[nt][1];
            s[nt][2] = __expf(s[nt][2] - mn1); sum1 += s[nt][2];
            s[nt][3] = __expf(s[nt][3] - mn1); sum1 += s[nt][3];
        }
        sum0 += __shfl_xor_sync(0xffffffffu, sum0, 1);
        sum0 += __shfl_xor_sync(0xffffffffu, sum0, 2);
        sum1 += __shfl_xor_sync(0xffffffffu, sum1, 1);
        sum1 += __shfl_xor_sync(0xffffffffu, sum1, 2);
        l0 = l0 * al0 + sum0;
        l1 = l1 * al1 + sum1;

        #pragma unroll
        for (int nt = 0; nt < 8; nt++) {
            o[nt][0] *= al0; o[nt][1] *= al0;
            o[nt][2] *= al1; o[nt][3] *= al1;
        }

        // publish P (q,key) for this warp's rows
        #pragma unroll
        for (int nt = 0; nt < 8; nt++) {
            const int cc = nt * 8 + t * 2;
            Ps[(m0 + g    ) * QP + cc    ] = f2tf(s[nt][0]);
            Ps[(m0 + g    ) * QP + cc + 1] = f2tf(s[nt][1]);
            Ps[(m0 + g + 8) * QP + cc    ] = f2tf(s[nt][2]);
            Ps[(m0 + g + 8) * QP + cc + 1] = f2tf(s[nt][3]);
        }
        __syncwarp();

        // ---- O += P @ V  (k = key 64, n = d 64) ----
        #pragma unroll
        for (int ks = 0; ks < 8; ks++) {
            const int kb = ks * 8;
            unsigned a[4], bfr[8][2];
            a[0] = __float_as_uint(Ps[(m0 + g    ) * QP + kb + t    ]);
            a[1] = __float_as_uint(Ps[(m0 + g + 8) * QP + kb + t    ]);
            a[2] = __float_as_uint(Ps[(m0 + g    ) * QP + kb + t + 4]);
            a[3] = __float_as_uint(Ps[(m0 + g + 8) * QP + kb + t + 4]);
            #pragma unroll
            for (int nt = 0; nt < 8; nt++) {
                bfr[nt][0] = __float_as_uint(Vs[(kb + t    ) * KP + nt * 8 + g]);
                bfr[nt][1] = __float_as_uint(Vs[(kb + t + 4) * KP + nt * 8 + g]);
            }
            #pragma unroll
            for (int nt = 0; nt < 8; nt++)
                mma_tf32(o[nt], a, bfr[nt]);
        }
    }

    // normalize + store
    const float inv0 = 1.f / l0;
    const float inv1 = 1.f / l1;
    const int qr0 = q0 + m0 + g;
    #pragma unroll
    for (int nt = 0; nt < 8; nt++) {
        const int d = h * HS + nt * 8 + t * 2;
        float2 v0 = make_float2(o[nt][0] * inv0, o[nt][1] * inv0);
        float2 v1 = make_float2(o[nt][2] * inv1, o[nt][3] * inv1);
        *(float2*)&attn[((size_t)b * SS + qr0    ) * HIDDEN + d] = v0;
        *(float2*)&attn[((size_t)b * SS + qr0 + 8) * HIDDEN + d] = v1;
    }
}

// ---------------------------------------------------------------------------
extern "C" void kernel_launch(void* const* d_in, const int* in_sizes, int n_in,
                              void* d_out, int out_size)
{
    (void)in_sizes; (void)n_in; (void)out_size;
    const float* x    = (const float*)d_in[0];
    const float* Wqkv = (const float*)d_in[1];
    const float* bqkv = (const float*)d_in[2];
    const float* Wo   = (const float*)d_in[3];
    const float* bo   = (const float*)d_in[4];
    float* out = (float*)d_out;

    float* qkv_buf = nullptr;
    float* attn_buf = nullptr;
    cudaGetSymbolAddress((void**)&qkv_buf, g_qkv);
    cudaGetSymbolAddress((void**)&attn_buf, g_attn);

    const int flash_smem = (128 * QP * 2 + 64 * KP * 2) * (int)sizeof(float); // 104 KB
    cudaFuncSetAttribute(flash_tf32_kernel,
                         cudaFuncAttributeMaxDynamicSharedMemorySize, flash_smem);

    // 1) QKV projection: [4096,1024] @ [1024,3072] + bqkv
    {
        dim3 grid(QKV_N / 128, M_TOT / 128);   // (24, 32)
        gemm_tf32_kernel<<<grid, 256>>>(x, Wqkv, bqkv, qkv_buf,
                                        M_TOT, QKV_N, HIDDEN);
    }
    // 2) Flash attention
    {
        dim3 grid(BB * NH, SS / 128);          // (32, 16)
        flash_tf32_kernel<<<grid, 256, flash_smem>>>(qkv_buf, attn_buf);
    }
    // 3) Output projection: [4096,1024] @ [1024,1024] + bo
    {
        dim3 grid(HIDDEN / 128, M_TOT / 128);  // (8, 32)
        gemm_tf32_kernel<<<grid, 256>>>(attn_buf, Wo, bo, out,
                                        M_TOT, HIDDEN, HIDDEN);
    }
}

// round 8
// speedup vs baseline: 3.3494x; 1.3742x over previous
#include <cuda_runtime.h>
#include <cstdint>

#define HIDDEN 1024
#define NH 16
#define HS 64
#define BB 2
#define SS 2048
#define M_TOT (BB*SS)       /* 4096 */
#define QKV_N (3*HIDDEN)    /* 3072 */

// Scratch buffers (static device globals — no runtime allocation).
__device__ float g_qkv[(size_t)M_TOT * QKV_N];    // 48 MB
__device__ float g_attn[(size_t)M_TOT * HIDDEN];  // 16 MB

// ---------------------------------------------------------------------------
// Helpers
// ---------------------------------------------------------------------------
__device__ __forceinline__ float f2tf(float x) {
    unsigned r;
    asm("cvt.rna.tf32.f32 %0, %1;" : "=r"(r) : "f"(x));
    return __uint_as_float(r);
}
__device__ __forceinline__ unsigned f2tfu(float x) {
    unsigned r;
    asm("cvt.rna.tf32.f32 %0, %1;" : "=r"(r) : "f"(x));
    return r;
}

__device__ __forceinline__ void mma_tf32(float* c, const unsigned* a, const unsigned* b) {
    asm volatile(
        "mma.sync.aligned.m16n8k8.row.col.f32.tf32.tf32.f32 "
        "{%0,%1,%2,%3}, {%4,%5,%6,%7}, {%8,%9}, {%0,%1,%2,%3};\n"
        : "+f"(c[0]), "+f"(c[1]), "+f"(c[2]), "+f"(c[3])
        : "r"(a[0]), "r"(a[1]), "r"(a[2]), "r"(a[3]),
          "r"(b[0]), "r"(b[1]));
}

__device__ __forceinline__ void cpa16(float* dst, const float* src) {
    unsigned d = (unsigned)__cvta_generic_to_shared(dst);
    asm volatile("cp.async.cg.shared.global [%0], [%1], 16;\n" :: "r"(d), "l"(src));
}
__device__ __forceinline__ void cp_commit() { asm volatile("cp.async.commit_group;\n"); }
__device__ __forceinline__ void cp_wait1() { asm volatile("cp.async.wait_group 1;\n" ::: "memory"); }
__device__ __forceinline__ void cp_wait0() { asm volatile("cp.async.wait_group 0;\n" ::: "memory"); }

// ---------------------------------------------------------------------------
// TF32 GEMM, cp.async double-buffered: C[M,N] = A[M,K] @ B[K,N] + bias[N]
// BM=BN=128, BK=32; 8 warps 4(m)x2(n), warp tile 32x64.
// As [m][k] pitch 36 (A-frag bank = 4g+t, conflict-free)
// Bs [k][n] pitch 136 (B-frag bank = 8t+g, conflict-free)
// tf32 rounding applied at fragment load (same numerics as before).
// ---------------------------------------------------------------------------
#define GAP 36
#define GBP 136

__global__ __launch_bounds__(256, 2) void gemm_tf32_kernel(
    const float* __restrict__ A, const float* __restrict__ B,
    const float* __restrict__ bias, float* __restrict__ C,
    int M, int N, int K)
{
    extern __shared__ float sm[];
    float* As = sm;                       // [2][128*36]
    float* Bs = sm + 2 * 128 * GAP;       // [2][32*136]

    const int tid  = threadIdx.x;
    const int lane = tid & 31;
    const int wid  = tid >> 5;
    const int g = lane >> 2, t = lane & 3;
    const int wm = (wid & 3) * 32;
    const int wn = (wid >> 2) * 64;
    const int row0 = blockIdx.y * 128;
    const int col0 = blockIdx.x * 128;

    float c[2][8][4] = {};
    const int NIT = K / 32;

    auto load_tile = [&](int it, int buf) {
        const int k0 = it * 32;
        float* Ab = As + buf * (128 * GAP);
        float* Bb = Bs + buf * (32 * GBP);
        #pragma unroll
        for (int i = 0; i < 4; i++) {           // A: 128 rows x 8 chunks
            const int ch = tid + 256 * i;
            const int r = ch >> 3, sg = (ch & 7) * 4;
            cpa16(Ab + r * GAP + sg, &A[(size_t)(row0 + r) * K + k0 + sg]);
        }
        #pragma unroll
        for (int i = 0; i < 4; i++) {           // B: 32 rows x 32 chunks
            const int ch = tid + 256 * i;
            const int kk = ch >> 5, sg = (ch & 31) * 4;
            cpa16(Bb + kk * GBP + sg, &B[(size_t)(k0 + kk) * N + col0 + sg]);
        }
        cp_commit();
    };

    load_tile(0, 0);
    for (int it = 0; it < NIT; it++) {
        const int buf = it & 1;
        if (it + 1 < NIT) { load_tile(it + 1, buf ^ 1); cp_wait1(); }
        else              { cp_wait0(); }
        __syncthreads();

        const float* Ab = As + buf * (128 * GAP);
        const float* Bb = Bs + buf * (32 * GBP);
        #pragma unroll
        for (int ks = 0; ks < 4; ks++) {
            const int kb = ks * 8;
            unsigned a[2][4], b[8][2];
            #pragma unroll
            for (int mt = 0; mt < 2; mt++) {
                const int mb = wm + mt * 16;
                a[mt][0] = f2tfu(Ab[(mb + g    ) * GAP + kb + t    ]);
                a[mt][1] = f2tfu(Ab[(mb + g + 8) * GAP + kb + t    ]);
                a[mt][2] = f2tfu(Ab[(mb + g    ) * GAP + kb + t + 4]);
                a[mt][3] = f2tfu(Ab[(mb + g + 8) * GAP + kb + t + 4]);
            }
            #pragma unroll
            for (int nt = 0; nt < 8; nt++) {
                b[nt][0] = f2tfu(Bb[(kb + t    ) * GBP + wn + nt * 8 + g]);
                b[nt][1] = f2tfu(Bb[(kb + t + 4) * GBP + wn + nt * 8 + g]);
            }
            #pragma unroll
            for (int mt = 0; mt < 2; mt++)
                #pragma unroll
                for (int nt = 0; nt < 8; nt++)
                    mma_tf32(c[mt][nt], a[mt], b[nt]);
        }
        __syncthreads();
    }

    #pragma unroll
    for (int mt = 0; mt < 2; mt++) {
        const int r = row0 + wm + mt * 16 + g;
        #pragma unroll
        for (int nt = 0; nt < 8; nt++) {
            const int cn = col0 + wn + nt * 8 + t * 2;
            const float b0 = bias[cn], b1 = bias[cn + 1];
            float2 v0 = make_float2(c[mt][nt][0] + b0, c[mt][nt][1] + b1);
            float2 v1 = make_float2(c[mt][nt][2] + b0, c[mt][nt][3] + b1);
            *(float2*)&C[(size_t)r * N + cn]       = v0;
            *(float2*)&C[(size_t)(r + 8) * N + cn] = v1;
        }
    }
}
#define GEMM_SMEM ((2 * 128 * GAP + 2 * 32 * GBP) * (int)sizeof(float))  /* 71680 */

// ---------------------------------------------------------------------------
// Flash attention v2: no K transpose (K row-major IS col-major K^T for mma),
// cp.async double-buffered K/V, Q fragments register-resident, Qs aliased as Ps.
//   QsPs[128][68]  Q staging then P tile (A-frag bank 4g+t, conflict-free)
//   Ks[2][64][68]  (B-frag bank 4g+t, conflict-free)
//   Vs[2][64][72]  (B-frag bank 8t+g, conflict-free)
// ---------------------------------------------------------------------------
#define FQP 68
#define FKP 68
#define FVP 72
#define FLASH_SMEM ((128 * FQP + 2 * 64 * FKP + 2 * 64 * FVP) * (int)sizeof(float)) /* 106496 */

__global__ __launch_bounds__(256) void flash_tf32_kernel(
    const float* __restrict__ qkv, float* __restrict__ attn)
{
    extern __shared__ float sm[];
    float* QsPs = sm;                         // 128*68
    float* Ks   = QsPs + 128 * FQP;           // [2][64*68]
    float* Vs   = Ks + 2 * 64 * FKP;          // [2][64*72]

    const int bh = blockIdx.x;
    const int b = bh / NH, h = bh % NH;
    const int q0 = blockIdx.y * 128;
    const int tid = threadIdx.x;
    const int lane = tid & 31;
    const int wid = tid >> 5;
    const int g = lane >> 2, t = lane & 3;
    const int m0 = wid * 16;

    const float scale = 0.125f;
    const float* qbase = qkv + (size_t)b * SS * QKV_N + h * HS;
    const float* kbase = qbase + HIDDEN;
    const float* vbase = qbase + 2 * HIDDEN;

    auto load_kv = [&](int it, int buf) {
        const int k0 = it * 64;
        float* Kb = Ks + buf * (64 * FKP);
        float* Vb = Vs + buf * (64 * FVP);
        #pragma unroll
        for (int i = 0; i < 4; i++) {        // K: 64 rows x 16 chunks
            const int ch = tid + 256 * i;
            const int key = ch >> 4, sg = (ch & 15) * 4;
            cpa16(Kb + key * FKP + sg, &kbase[(size_t)(k0 + key) * QKV_N + sg]);
        }
        #pragma unroll
        for (int i = 0; i < 4; i++) {        // V
            const int ch = tid + 256 * i;
            const int key = ch >> 4, sg = (ch & 15) * 4;
            cpa16(Vb + key * FVP + sg, &vbase[(size_t)(k0 + key) * QKV_N + sg]);
        }
        cp_commit();
    };

    // Start K/V tile 0 ASAP, then stage Q (scaled + tf32) into QsPs.
    load_kv(0, 0);
    #pragma unroll
    for (int i = 0; i < 8; i++) {
        const int e = tid + 256 * i;
        const int r = e >> 4;
        const int dc = (e & 15) * 4;
        float4 q4 = *(const float4*)&qbase[(size_t)(q0 + r) * QKV_N + dc];
        q4.x = f2tf(q4.x * scale); q4.y = f2tf(q4.y * scale);
        q4.z = f2tf(q4.z * scale); q4.w = f2tf(q4.w * scale);
        *(float4*)&QsPs[r * FQP + dc] = q4;
    }
    __syncthreads();

    // Q fragments -> registers (reused for all 32 key tiles).
    unsigned qf[8][4];
    #pragma unroll
    for (int ks = 0; ks < 8; ks++) {
        const int kb = ks * 8;
        qf[ks][0] = __float_as_uint(QsPs[(m0 + g    ) * FQP + kb + t    ]);
        qf[ks][1] = __float_as_uint(QsPs[(m0 + g + 8) * FQP + kb + t    ]);
        qf[ks][2] = __float_as_uint(QsPs[(m0 + g    ) * FQP + kb + t + 4]);
        qf[ks][3] = __float_as_uint(QsPs[(m0 + g + 8) * FQP + kb + t + 4]);
    }

    float o[8][4] = {};
    float mrow0 = -1e30f, mrow1 = -1e30f, l0 = 0.f, l1 = 0.f;

    const int NT = SS / 64;
    for (int it = 0; it < NT; it++) {
        const int buf = it & 1;
        if (it + 1 < NT) { load_kv(it + 1, buf ^ 1); cp_wait1(); }
        else             { cp_wait0(); }
        __syncthreads();

        const float* Kb = Ks + buf * (64 * FKP);
        const float* Vb = Vs + buf * (64 * FVP);

        // ---- S = Q @ K^T ----
        float s[8][4] = {};
        #pragma unroll
        for (int ks = 0; ks < 8; ks++) {
            const int kb = ks * 8;
            unsigned bfr[8][2];
            #pragma unroll
            for (int nt = 0; nt < 8; nt++) {
                bfr[nt][0] = f2tfu(Kb[(nt * 8 + g) * FKP + kb + t    ]);
                bfr[nt][1] = f2tfu(Kb[(nt * 8 + g) * FKP + kb + t + 4]);
            }
            #pragma unroll
            for (int nt = 0; nt < 8; nt++)
                mma_tf32(s[nt], qf[ks], bfr[nt]);
        }

        // ---- online softmax ----
        float mx0 = -1e30f, mx1 = -1e30f;
        #pragma unroll
        for (int nt = 0; nt < 8; nt++) {
            mx0 = fmaxf(mx0, fmaxf(s[nt][0], s[nt][1]));
            mx1 = fmaxf(mx1, fmaxf(s[nt][2], s[nt][3]));
        }
        mx0 = fmaxf(mx0, __shfl_xor_sync(0xffffffffu, mx0, 1));
        mx0 = fmaxf(mx0, __shfl_xor_sync(0xffffffffu, mx0, 2));
        mx1 = fmaxf(mx1, __shfl_xor_sync(0xffffffffu, mx1, 1));
        mx1 = fmaxf(mx1, __shfl_xor_sync(0xffffffffu, mx1, 2));

        const float mn0 = fmaxf(mrow0, mx0);
        const float mn1 = fmaxf(mrow1, mx1);
        const float al0 = __expf(mrow0 - mn0);
        const float al1 = __expf(mrow1 - mn1);
        mrow0 = mn0; mrow1 = mn1;

        float sum0 = 0.f, sum1 = 0.f;
        #pragma unroll
        for (int nt = 0; nt < 8; nt++) {
            s[nt][0] = __expf(s[nt][0] - mn0); sum0 += s[nt][0];
            s[nt][1] = __expf(s[nt][1] - mn0); sum0 += s[nt][1];
            s[nt][2] = __expf(s[nt][2] - mn1); sum1 += s[nt][2];
            s[nt][3] = __expf(s[nt][3] - mn1); sum1 += s[nt][3];
        }
        sum0 += __shfl_xor_sync(0xffffffffu, sum0, 1);
        sum0 += __shfl_xor_sync(0xffffffffu, sum0, 2);
        sum1 += __shfl_xor_sync(0xffffffffu, sum1, 1);
        sum1 += __shfl_xor_sync(0xffffffffu, sum1, 2);
        l0 = l0 * al0 + sum0;
        l1 = l1 * al1 + sum1;

        #pragma unroll
        for (int nt = 0; nt < 8; nt++) {
            o[nt][0] *= al0; o[nt][1] *= al0;
            o[nt][2] *= al1; o[nt][3] *= al1;
        }

        // publish P (per-warp rows; QsPs alias is safe: each warp touches only its rows)
        #pragma unroll
        for (int nt = 0; nt < 8; nt++) {
            const int cc = nt * 8 + t * 2;
            QsPs[(m0 + g    ) * FQP + cc    ] = f2tf(s[nt][0]);
            QsPs[(m0 + g    ) * FQP + cc + 1] = f2tf(s[nt][1]);
            QsPs[(m0 + g + 8) * FQP + cc    ] = f2tf(s[nt][2]);
            QsPs[(m0 + g + 8) * FQP + cc + 1] = f2tf(s[nt][3]);
        }
        __syncwarp();

        // ---- O += P @ V ----
        #pragma unroll
        for (int ks = 0; ks < 8; ks++) {
            const int kb = ks * 8;
            unsigned a[4], bfr[8][2];
            a[0] = __float_as_uint(QsPs[(m0 + g    ) * FQP + kb + t    ]);
            a[1] = __float_as_uint(QsPs[(m0 + g + 8) * FQP + kb + t    ]);
            a[2] = __float_as_uint(QsPs[(m0 + g    ) * FQP + kb + t + 4]);
            a[3] = __float_as_uint(QsPs[(m0 + g + 8) * FQP + kb + t + 4]);
            #pragma unroll
            for (int nt = 0; nt < 8; nt++) {
                bfr[nt][0] = f2tfu(Vb[(kb + t    ) * FVP + nt * 8 + g]);
                bfr[nt][1] = f2tfu(Vb[(kb + t + 4) * FVP + nt * 8 + g]);
            }
            #pragma unroll
            for (int nt = 0; nt < 8; nt++)
                mma_tf32(o[nt], a, bfr[nt]);
        }
        __syncthreads();   // all warps done with Kb/Vb before next-next tile lands
    }

    // normalize + store
    const float inv0 = 1.f / l0;
    const float inv1 = 1.f / l1;
    const int qr0 = q0 + m0 + g;
    #pragma unroll
    for (int nt = 0; nt < 8; nt++) {
        const int d = h * HS + nt * 8 + t * 2;
        float2 v0 = make_float2(o[nt][0] * inv0, o[nt][1] * inv0);
        float2 v1 = make_float2(o[nt][2] * inv1, o[nt][3] * inv1);
        *(float2*)&attn[((size_t)b * SS + qr0    ) * HIDDEN + d] = v0;
        *(float2*)&attn[((size_t)b * SS + qr0 + 8) * HIDDEN + d] = v1;
    }
}

// ---------------------------------------------------------------------------
extern "C" void kernel_launch(void* const* d_in, const int* in_sizes, int n_in,
                              void* d_out, int out_size)
{
    (void)in_sizes; (void)n_in; (void)out_size;
    const float* x    = (const float*)d_in[0];
    const float* Wqkv = (const float*)d_in[1];
    const float* bqkv = (const float*)d_in[2];
    const float* Wo   = (const float*)d_in[3];
    const float* bo   = (const float*)d_in[4];
    float* out = (float*)d_out;

    float* qkv_buf = nullptr;
    float* attn_buf = nullptr;
    cudaGetSymbolAddress((void**)&qkv_buf, g_qkv);
    cudaGetSymbolAddress((void**)&attn_buf, g_attn);

    cudaFuncSetAttribute(gemm_tf32_kernel,
                         cudaFuncAttributeMaxDynamicSharedMemorySize, GEMM_SMEM);
    cudaFuncSetAttribute(flash_tf32_kernel,
                         cudaFuncAttributeMaxDynamicSharedMemorySize, FLASH_SMEM);

    // 1) QKV projection
    {
        dim3 grid(QKV_N / 128, M_TOT / 128);   // (24, 32)
        gemm_tf32_kernel<<<grid, 256, GEMM_SMEM>>>(x, Wqkv, bqkv, qkv_buf,
                                                   M_TOT, QKV_N, HIDDEN);
    }
    // 2) Flash attention
    {
        dim3 grid(BB * NH, SS / 128);          // (32, 16)
        flash_tf32_kernel<<<grid, 256, FLASH_SMEM>>>(qkv_buf, attn_buf);
    }
    // 3) Output projection
    {
        dim3 grid(HIDDEN / 128, M_TOT / 128);  // (8, 32)
        gemm_tf32_kernel<<<grid, 256, GEMM_SMEM>>>(attn_buf, Wo, bo, out,
                                                   M_TOT, HIDDEN, HIDDEN);
    }
}

// round 10
// speedup vs baseline: 3.5627x; 1.0637x over previous
#include <cuda_runtime.h>
#include <cstdint>

#define HIDDEN 1024
#define NH 16
#define HS 64
#define BB 2
#define SS 2048
#define M_TOT (BB*SS)       /* 4096 */
#define QKV_N (3*HIDDEN)    /* 3072 */

// Scratch buffers (static device globals — no runtime allocation).
__device__ float g_qkv[(size_t)M_TOT * QKV_N];     // 48 MB (stored tf32-valued)
__device__ float g_attn[(size_t)M_TOT * HIDDEN];   // 16 MB (stored tf32-valued)
__device__ float g_x_tf[(size_t)M_TOT * HIDDEN];   // 16 MB
__device__ float g_wqkv_tf[(size_t)HIDDEN * QKV_N];// 12.6 MB
__device__ float g_wo_tf[(size_t)HIDDEN * HIDDEN]; // 4.2 MB

// ---------------------------------------------------------------------------
// Helpers
// ---------------------------------------------------------------------------
__device__ __forceinline__ float f2tf(float x) {
    unsigned r;
    asm("cvt.rna.tf32.f32 %0, %1;" : "=r"(r) : "f"(x));
    return __uint_as_float(r);
}

__device__ __forceinline__ void mma_tf32(float* c, const unsigned* a, const unsigned* b) {
    asm volatile(
        "mma.sync.aligned.m16n8k8.row.col.f32.tf32.tf32.f32 "
        "{%0,%1,%2,%3}, {%4,%5,%6,%7}, {%8,%9}, {%0,%1,%2,%3};\n"
        : "+f"(c[0]), "+f"(c[1]), "+f"(c[2]), "+f"(c[3])
        : "r"(a[0]), "r"(a[1]), "r"(a[2]), "r"(a[3]),
          "r"(b[0]), "r"(b[1]));
}

__device__ __forceinline__ void cpa16(float* dst, const float* src) {
    unsigned d = (unsigned)__cvta_generic_to_shared(dst);
    asm volatile("cp.async.cg.shared.global [%0], [%1], 16;\n" :: "r"(d), "l"(src));
}
__device__ __forceinline__ void cp_commit() { asm volatile("cp.async.commit_group;\n"); }
__device__ __forceinline__ void cp_wait1() { asm volatile("cp.async.wait_group 1;\n" ::: "memory"); }
__device__ __forceinline__ void cp_wait0() { asm volatile("cp.async.wait_group 0;\n" ::: "memory"); }

// ---------------------------------------------------------------------------
// Prep: elementwise tf32 rounding (produces tf32-valued fp32 copies).
// ---------------------------------------------------------------------------
__global__ __launch_bounds__(256) void tf32_prep_kernel(
    const float4* __restrict__ in, float4* __restrict__ out, int n4)
{
    const int i = blockIdx.x * blockDim.x + threadIdx.x;
    if (i < n4) {
        float4 v = in[i];
        v.x = f2tf(v.x); v.y = f2tf(v.y); v.z = f2tf(v.z); v.w = f2tf(v.w);
        out[i] = v;
    }
}

// ---------------------------------------------------------------------------
// TF32 GEMM, cp.async double-buffered: C[M,N] = A[M,K] @ B[K,N] + bias[N]
// A and B must already be tf32-valued. round_out=1 -> round C for downstream.
// As [m][k] pitch 36 (A-frag bank = 4g+t, conflict-free)
// Bs [k][n] pitch 136 (B-frag bank = 8t+g, conflict-free)
// ---------------------------------------------------------------------------
#define GAP 36
#define GBP 136

__global__ __launch_bounds__(256, 2) void gemm_tf32_kernel(
    const float* __restrict__ A, const float* __restrict__ B,
    const float* __restrict__ bias, float* __restrict__ C,
    int M, int N, int K, int round_out)
{
    extern __shared__ float sm[];
    float* As = sm;                       // [2][128*36]
    float* Bs = sm + 2 * 128 * GAP;       // [2][32*136]

    const int tid  = threadIdx.x;
    const int lane = tid & 31;
    const int wid  = tid >> 5;
    const int g = lane >> 2, t = lane & 3;
    const int wm = (wid & 3) * 32;
    const int wn = (wid >> 2) * 64;
    const int row0 = blockIdx.y * 128;
    const int col0 = blockIdx.x * 128;

    float c[2][8][4] = {};
    const int NIT = K / 32;

    auto load_tile = [&](int it, int buf) {
        const int k0 = it * 32;
        float* Ab = As + buf * (128 * GAP);
        float* Bb = Bs + buf * (32 * GBP);
        #pragma unroll
        for (int i = 0; i < 4; i++) {           // A: 128 rows x 8 chunks
            const int ch = tid + 256 * i;
            const int r = ch >> 3, sg = (ch & 7) * 4;
            cpa16(Ab + r * GAP + sg, &A[(size_t)(row0 + r) * K + k0 + sg]);
        }
        #pragma unroll
        for (int i = 0; i < 4; i++) {           // B: 32 rows x 32 chunks
            const int ch = tid + 256 * i;
            const int kk = ch >> 5, sg = (ch & 31) * 4;
            cpa16(Bb + kk * GBP + sg, &B[(size_t)(k0 + kk) * N + col0 + sg]);
        }
        cp_commit();
    };

    load_tile(0, 0);
    for (int it = 0; it < NIT; it++) {
        const int buf = it & 1;
        if (it + 1 < NIT) { load_tile(it + 1, buf ^ 1); cp_wait1(); }
        else              { cp_wait0(); }
        __syncthreads();

        const float* Ab = As + buf * (128 * GAP);
        const float* Bb = Bs + buf * (32 * GBP);
        #pragma unroll
        for (int ks = 0; ks < 4; ks++) {
            const int kb = ks * 8;
            unsigned a[2][4], b[8][2];
            #pragma unroll
            for (int mt = 0; mt < 2; mt++) {
                const int mb = wm + mt * 16;
                a[mt][0] = __float_as_uint(Ab[(mb + g    ) * GAP + kb + t    ]);
                a[mt][1] = __float_as_uint(Ab[(mb + g + 8) * GAP + kb + t    ]);
                a[mt][2] = __float_as_uint(Ab[(mb + g    ) * GAP + kb + t + 4]);
                a[mt][3] = __float_as_uint(Ab[(mb + g + 8) * GAP + kb + t + 4]);
            }
            #pragma unroll
            for (int nt = 0; nt < 8; nt++) {
                b[nt][0] = __float_as_uint(Bb[(kb + t    ) * GBP + wn + nt * 8 + g]);
                b[nt][1] = __float_as_uint(Bb[(kb + t + 4) * GBP + wn + nt * 8 + g]);
            }
            #pragma unroll
            for (int mt = 0; mt < 2; mt++)
                #pragma unroll
                for (int nt = 0; nt < 8; nt++)
                    mma_tf32(c[mt][nt], a[mt], b[nt]);
        }
        __syncthreads();
    }

    #pragma unroll
    for (int mt = 0; mt < 2; mt++) {
        const int r = row0 + wm + mt * 16 + g;
        #pragma unroll
        for (int nt = 0; nt < 8; nt++) {
            const int cn = col0 + wn + nt * 8 + t * 2;
            const float b0 = bias[cn], b1 = bias[cn + 1];
            float2 v0 = make_float2(c[mt][nt][0] + b0, c[mt][nt][1] + b1);
            float2 v1 = make_float2(c[mt][nt][2] + b0, c[mt][nt][3] + b1);
            if (round_out) {
                v0.x = f2tf(v0.x); v0.y = f2tf(v0.y);
                v1.x = f2tf(v1.x); v1.y = f2tf(v1.y);
            }
            *(float2*)&C[(size_t)r * N + cn]       = v0;
            *(float2*)&C[(size_t)(r + 8) * N + cn] = v1;
        }
    }
}
#define GEMM_SMEM ((2 * 128 * GAP + 2 * 32 * GBP) * (int)sizeof(float))  /* 71680 */

// ---------------------------------------------------------------------------
// Flash attention v3: qkv is tf32-valued (no cvt anywhere in the loop).
//   QsPs[128][68]  Q staging then P tile (A-frag bank 4g+t, conflict-free)
//   Ks[2][64][68]  row-major K == col-major K^T for mma (bank 4g+t)
//   Vs[2][64][72]  (bank 8t+g)
// Writes attn tf32-rounded (consumed by tf32 out-proj; rounding idempotent).
// ---------------------------------------------------------------------------
#define FQP 68
#define FKP 68
#define FVP 72
#define FLASH_SMEM ((128 * FQP + 2 * 64 * FKP + 2 * 64 * FVP) * (int)sizeof(float)) /* 106496 */

__global__ __launch_bounds__(256) void flash_tf32_kernel(
    const float* __restrict__ qkv, float* __restrict__ attn)
{
    extern __shared__ float sm[];
    float* QsPs = sm;                         // 128*68
    float* Ks   = QsPs + 128 * FQP;           // [2][64*68]
    float* Vs   = Ks + 2 * 64 * FKP;          // [2][64*72]

    const int bh = blockIdx.x;
    const int b = bh / NH, h = bh % NH;
    const int q0 = blockIdx.y * 128;
    const int tid = threadIdx.x;
    const int lane = tid & 31;
    const int wid = tid >> 5;
    const int g = lane >> 2, t = lane & 3;
    const int m0 = wid * 16;

    const float scale = 0.125f;   // exact power of 2: q*scale stays tf32-valued
    const float* qbase = qkv + (size_t)b * SS * QKV_N + h * HS;
    const float* kbase = qbase + HIDDEN;
    const float* vbase = qbase + 2 * HIDDEN;

    auto load_kv = [&](int it, int buf) {
        const int k0 = it * 64;
        float* Kb = Ks + buf * (64 * FKP);
        float* Vb = Vs + buf * (64 * FVP);
        #pragma unroll
        for (int i = 0; i < 4; i++) {        // K: 64 rows x 16 chunks
            const int ch = tid + 256 * i;
            const int key = ch >> 4, sg = (ch & 15) * 4;
            cpa16(Kb + key * FKP + sg, &kbase[(size_t)(k0 + key) * QKV_N + sg]);
        }
        #pragma unroll
        for (int i = 0; i < 4; i++) {        // V
            const int ch = tid + 256 * i;
            const int key = ch >> 4, sg = (ch & 15) * 4;
            cpa16(Vb + key * FVP + sg, &vbase[(size_t)(k0 + key) * QKV_N + sg]);
        }
        cp_commit();
    };

    load_kv(0, 0);
    #pragma unroll
    for (int i = 0; i < 8; i++) {
        const int e = tid + 256 * i;
        const int r = e >> 4;
        const int dc = (e & 15) * 4;
        float4 q4 = *(const float4*)&qbase[(size_t)(q0 + r) * QKV_N + dc];
        q4.x *= scale; q4.y *= scale; q4.z *= scale; q4.w *= scale;
        *(float4*)&QsPs[r * FQP + dc] = q4;
    }
    __syncthreads();

    // Q fragments -> registers (reused for all 32 key tiles).
    unsigned qf[8][4];
    #pragma unroll
    for (int ks = 0; ks < 8; ks++) {
        const int kb = ks * 8;
        qf[ks][0] = __float_as_uint(QsPs[(m0 + g    ) * FQP + kb + t    ]);
        qf[ks][1] = __float_as_uint(QsPs[(m0 + g + 8) * FQP + kb + t    ]);
        qf[ks][2] = __float_as_uint(QsPs[(m0 + g    ) * FQP + kb + t + 4]);
        qf[ks][3] = __float_as_uint(QsPs[(m0 + g + 8) * FQP + kb + t + 4]);
    }

    float o[8][4] = {};
    float mrow0 = -1e30f, mrow1 = -1e30f, l0 = 0.f, l1 = 0.f;

    const int NT = SS / 64;
    for (int it = 0; it < NT; it++) {
        const int buf = it & 1;
        if (it + 1 < NT) { load_kv(it + 1, buf ^ 1); cp_wait1(); }
        else             { cp_wait0(); }
        __syncthreads();

        const float* Kb = Ks + buf * (64 * FKP);
        const float* Vb = Vs + buf * (64 * FVP);

        // ---- S = Q @ K^T ----
        float s[8][4] = {};
        #pragma unroll
        for (int ks = 0; ks < 8; ks++) {
            const int kb = ks * 8;
            unsigned bfr[8][2];
            #pragma unroll
            for (int nt = 0; nt < 8; nt++) {
                bfr[nt][0] = __float_as_uint(Kb[(nt * 8 + g) * FKP + kb + t    ]);
                bfr[nt][1] = __float_as_uint(Kb[(nt * 8 + g) * FKP + kb + t + 4]);
            }
            #pragma unroll
            for (int nt = 0; nt < 8; nt++)
                mma_tf32(s[nt], qf[ks], bfr[nt]);
        }

        // ---- online softmax ----
        float mx0 = -1e30f, mx1 = -1e30f;
        #pragma unroll
        for (int nt = 0; nt < 8; nt++) {
            mx0 = fmaxf(mx0, fmaxf(s[nt][0], s[nt][1]));
            mx1 = fmaxf(mx1, fmaxf(s[nt][2], s[nt][3]));
        }
        mx0 = fmaxf(mx0, __shfl_xor_sync(0xffffffffu, mx0, 1));
        mx0 = fmaxf(mx0, __shfl_xor_sync(0xffffffffu, mx0, 2));
        mx1 = fmaxf(mx1, __shfl_xor_sync(0xffffffffu, mx1, 1));
        mx1 = fmaxf(mx1, __shfl_xor_sync(0xffffffffu, mx1, 2));

        const float mn0 = fmaxf(mrow0, mx0);
        const float mn1 = fmaxf(mrow1, mx1);
        const float al0 = __expf(mrow0 - mn0);
        const float al1 = __expf(mrow1 - mn1);
        mrow0 = mn0; mrow1 = mn1;

        float sum0 = 0.f, sum1 = 0.f;
        #pragma unroll
        for (int nt = 0; nt < 8; nt++) {
            s[nt][0] = __expf(s[nt][0] - mn0); sum0 += s[nt][0];
            s[nt][1] = __expf(s[nt][1] - mn0); sum0 += s[nt][1];
            s[nt][2] = __expf(s[nt][2] - mn1); sum1 += s[nt][2];
            s[nt][3] = __expf(s[nt][3] - mn1); sum1 += s[nt][3];
        }
        sum0 += __shfl_xor_sync(0xffffffffu, sum0, 1);
        sum0 += __shfl_xor_sync(0xffffffffu, sum0, 2);
        sum1 += __shfl_xor_sync(0xffffffffu, sum1, 1);
        sum1 += __shfl_xor_sync(0xffffffffu, sum1, 2);
        l0 = l0 * al0 + sum0;
        l1 = l1 * al1 + sum1;

        #pragma unroll
        for (int nt = 0; nt < 8; nt++) {
            o[nt][0] *= al0; o[nt][1] *= al0;
            o[nt][2] *= al1; o[nt][3] *= al1;
        }

        // publish P tf32-rounded (per-warp rows; alias safe)
        #pragma unroll
        for (int nt = 0; nt < 8; nt++) {
            const int cc = nt * 8 + t * 2;
            QsPs[(m0 + g    ) * FQP + cc    ] = f2tf(s[nt][0]);
            QsPs[(m0 + g    ) * FQP + cc + 1] = f2tf(s[nt][1]);
            QsPs[(m0 + g + 8) * FQP + cc    ] = f2tf(s[nt][2]);
            QsPs[(m0 + g + 8) * FQP + cc + 1] = f2tf(s[nt][3]);
        }
        __syncwarp();

        // ---- O += P @ V ----
        #pragma unroll
        for (int ks = 0; ks < 8; ks++) {
            const int kb = ks * 8;
            unsigned a[4], bfr[8][2];
            a[0] = __float_as_uint(QsPs[(m0 + g    ) * FQP + kb + t    ]);
            a[1] = __float_as_uint(QsPs[(m0 + g + 8) * FQP + kb + t    ]);
            a[2] = __float_as_uint(QsPs[(m0 + g    ) * FQP + kb + t + 4]);
            a[3] = __float_as_uint(QsPs[(m0 + g + 8) * FQP + kb + t + 4]);
            #pragma unroll
            for (int nt = 0; nt < 8; nt++) {
                bfr[nt][0] = __float_as_uint(Vb[(kb + t    ) * FVP + nt * 8 + g]);
                bfr[nt][1] = __float_as_uint(Vb[(kb + t + 4) * FVP + nt * 8 + g]);
            }
            #pragma unroll
            for (int nt = 0; nt < 8; nt++)
                mma_tf32(o[nt], a, bfr[nt]);
        }
        __syncthreads();   // all warps done with Kb/Vb before next-next tile lands
    }

    // normalize + store (tf32-rounded: consumed by tf32 out-proj A operand)
    const float inv0 = 1.f / l0;
    const float inv1 = 1.f / l1;
    const int qr0 = q0 + m0 + g;
    #pragma unroll
    for (int nt = 0; nt < 8; nt++) {
        const int d = h * HS + nt * 8 + t * 2;
        float2 v0 = make_float2(f2tf(o[nt][0] * inv0), f2tf(o[nt][1] * inv0));
        float2 v1 = make_float2(f2tf(o[nt][2] * inv1), f2tf(o[nt][3] * inv1));
        *(float2*)&attn[((size_t)b * SS + qr0    ) * HIDDEN + d] = v0;
        *(float2*)&attn[((size_t)b * SS + qr0 + 8) * HIDDEN + d] = v1;
    }
}

// ---------------------------------------------------------------------------
extern "C" void kernel_launch(void* const* d_in, const int* in_sizes, int n_in,
                              void* d_out, int out_size)
{
    (void)in_sizes; (void)n_in; (void)out_size;
    const float* x    = (const float*)d_in[0];
    const float* Wqkv = (const float*)d_in[1];
    const float* bqkv = (const float*)d_in[2];
    const float* Wo   = (const float*)d_in[3];
    const float* bo   = (const float*)d_in[4];
    float* out = (float*)d_out;

    float *qkv_buf, *attn_buf, *x_tf, *wqkv_tf, *wo_tf;
    cudaGetSymbolAddress((void**)&qkv_buf, g_qkv);
    cudaGetSymbolAddress((void**)&attn_buf, g_attn);
    cudaGetSymbolAddress((void**)&x_tf, g_x_tf);
    cudaGetSymbolAddress((void**)&wqkv_tf, g_wqkv_tf);
    cudaGetSymbolAddress((void**)&wo_tf, g_wo_tf);

    cudaFuncSetAttribute(gemm_tf32_kernel,
                         cudaFuncAttributeMaxDynamicSharedMemorySize, GEMM_SMEM);
    cudaFuncSetAttribute(flash_tf32_kernel,
                         cudaFuncAttributeMaxDynamicSharedMemorySize, FLASH_SMEM);

    // 0) tf32-round inputs once (x, Wqkv, Wo)
    {
        const int nx = M_TOT * HIDDEN / 4;
        tf32_prep_kernel<<<(nx + 255) / 256, 256>>>((const float4*)x, (float4*)x_tf, nx);
        const int nw = HIDDEN * QKV_N / 4;
        tf32_prep_kernel<<<(nw + 255) / 256, 256>>>((const float4*)Wqkv, (float4*)wqkv_tf, nw);
        const int no = HIDDEN * HIDDEN / 4;
        tf32_prep_kernel<<<(no + 255) / 256, 256>>>((const float4*)Wo, (float4*)wo_tf, no);
    }
    // 1) QKV projection (output rounded for flash)
    {
        dim3 grid(QKV_N / 128, M_TOT / 128);   // (24, 32)
        gemm_tf32_kernel<<<grid, 256, GEMM_SMEM>>>(x_tf, wqkv_tf, bqkv, qkv_buf,
                                                   M_TOT, QKV_N, HIDDEN, 1);
    }
    // 2) Flash attention (output rounded for out-proj)
    {
        dim3 grid(BB * NH, SS / 128);          // (32, 16)
        flash_tf32_kernel<<<grid, 256, FLASH_SMEM>>>(qkv_buf, attn_buf);
    }
    // 3) Output projection (final output, unrounded)
    {
        dim3 grid(HIDDEN / 128, M_TOT / 128);  // (8, 32)
        gemm_tf32_kernel<<<grid, 256, GEMM_SMEM>>>(attn_buf, wo_tf, bo, out,
                                                   M_TOT, HIDDEN, HIDDEN, 0);
    }
}

// round 13
// speedup vs baseline: 3.7994x; 1.0664x over previous
#include <cuda_runtime.h>
#include <cstdint>

#define HIDDEN 1024
#define NH 16
#define HS 64
#define BB 2
#define SS 2048
#define M_TOT (BB*SS)       /* 4096 */
#define QKV_N (3*HIDDEN)    /* 3072 */

// Scratch buffers (static device globals — no runtime allocation).
__device__ float g_qkv[(size_t)M_TOT * QKV_N];     // 48 MB (stored tf32-valued)
__device__ float g_attn[(size_t)M_TOT * HIDDEN];   // 16 MB (stored tf32-valued)
__device__ float g_x_tf[(size_t)M_TOT * HIDDEN];   // 16 MB
__device__ float g_wqkv_tf[(size_t)HIDDEN * QKV_N];// 12.6 MB
__device__ float g_wo_tf[(size_t)HIDDEN * HIDDEN]; // 4.2 MB

// ---------------------------------------------------------------------------
// Helpers
// ---------------------------------------------------------------------------
__device__ __forceinline__ float f2tf(float x) {
    unsigned r;
    asm("cvt.rna.tf32.f32 %0, %1;" : "=r"(r) : "f"(x));
    return __uint_as_float(r);
}

__device__ __forceinline__ void mma_tf32(float* c, const unsigned* a, const unsigned* b) {
    asm volatile(
        "mma.sync.aligned.m16n8k8.row.col.f32.tf32.tf32.f32 "
        "{%0,%1,%2,%3}, {%4,%5,%6,%7}, {%8,%9}, {%0,%1,%2,%3};\n"
        : "+f"(c[0]), "+f"(c[1]), "+f"(c[2]), "+f"(c[3])
        : "r"(a[0]), "r"(a[1]), "r"(a[2]), "r"(a[3]),
          "r"(b[0]), "r"(b[1]));
}

__device__ __forceinline__ void cpa16(float* dst, const float* src) {
    unsigned d = (unsigned)__cvta_generic_to_shared(dst);
    asm volatile("cp.async.cg.shared.global [%0], [%1], 16;\n" :: "r"(d), "l"(src));
}
__device__ __forceinline__ void cp_commit() { asm volatile("cp.async.commit_group;\n"); }
__device__ __forceinline__ void cp_wait1() { asm volatile("cp.async.wait_group 1;\n" ::: "memory"); }
__device__ __forceinline__ void cp_wait0() { asm volatile("cp.async.wait_group 0;\n" ::: "memory"); }

// ---------------------------------------------------------------------------
// Prep: elementwise tf32 rounding (produces tf32-valued fp32 copies).
// ---------------------------------------------------------------------------
__global__ __launch_bounds__(256) void tf32_prep_kernel(
    const float4* __restrict__ in, float4* __restrict__ out, int n4)
{
    const int i = blockIdx.x * blockDim.x + threadIdx.x;
    if (i < n4) {
        float4 v = in[i];
        v.x = f2tf(v.x); v.y = f2tf(v.y); v.z = f2tf(v.z); v.w = f2tf(v.w);
        out[i] = v;
    }
}

// ---------------------------------------------------------------------------
// TF32 GEMM, cp.async double-buffered: C[M,N] = A[M,K] @ B[K,N] + bias[N]
// A and B must already be tf32-valued. round_out=1 -> round C for downstream.
// As [m][k] pitch 36 (A-frag bank = 4g+t, conflict-free)
// Bs [k][n] pitch 136 (B-frag bank = 8t+g, conflict-free)
// ---------------------------------------------------------------------------
#define GAP 36
#define GBP 136

__global__ __launch_bounds__(256, 2) void gemm_tf32_kernel(
    const float* __restrict__ A, const float* __restrict__ B,
    const float* __restrict__ bias, float* __restrict__ C,
    int M, int N, int K, int round_out)
{
    extern __shared__ float sm[];
    float* As = sm;                       // [2][128*36]
    float* Bs = sm + 2 * 128 * GAP;       // [2][32*136]

    const int tid  = threadIdx.x;
    const int lane = tid & 31;
    const int wid  = tid >> 5;
    const int g = lane >> 2, t = lane & 3;
    const int wm = (wid & 3) * 32;
    const int wn = (wid >> 2) * 64;
    const int row0 = blockIdx.y * 128;
    const int col0 = blockIdx.x * 128;

    float c[2][8][4] = {};
    const int NIT = K / 32;

    auto load_tile = [&](int it, int buf) {
        const int k0 = it * 32;
        float* Ab = As + buf * (128 * GAP);
        float* Bb = Bs + buf * (32 * GBP);
        #pragma unroll
        for (int i = 0; i < 4; i++) {           // A: 128 rows x 8 chunks
            const int ch = tid + 256 * i;
            const int r = ch >> 3, sg = (ch & 7) * 4;
            cpa16(Ab + r * GAP + sg, &A[(size_t)(row0 + r) * K + k0 + sg]);
        }
        #pragma unroll
        for (int i = 0; i < 4; i++) {           // B: 32 rows x 32 chunks
            const int ch = tid + 256 * i;
            const int kk = ch >> 5, sg = (ch & 31) * 4;
            cpa16(Bb + kk * GBP + sg, &B[(size_t)(k0 + kk) * N + col0 + sg]);
        }
        cp_commit();
    };

    load_tile(0, 0);
    for (int it = 0; it < NIT; it++) {
        const int buf = it & 1;
        if (it + 1 < NIT) { load_tile(it + 1, buf ^ 1); cp_wait1(); }
        else              { cp_wait0(); }
        __syncthreads();

        const float* Ab = As + buf * (128 * GAP);
        const float* Bb = Bs + buf * (32 * GBP);
        #pragma unroll
        for (int ks = 0; ks < 4; ks++) {
            const int kb = ks * 8;
            unsigned a[2][4], b[8][2];
            #pragma unroll
            for (int mt = 0; mt < 2; mt++) {
                const int mb = wm + mt * 16;
                a[mt][0] = __float_as_uint(Ab[(mb + g    ) * GAP + kb + t    ]);
                a[mt][1] = __float_as_uint(Ab[(mb + g + 8) * GAP + kb + t    ]);
                a[mt][2] = __float_as_uint(Ab[(mb + g    ) * GAP + kb + t + 4]);
                a[mt][3] = __float_as_uint(Ab[(mb + g + 8) * GAP + kb + t + 4]);
            }
            #pragma unroll
            for (int nt = 0; nt < 8; nt++) {
                b[nt][0] = __float_as_uint(Bb[(kb + t    ) * GBP + wn + nt * 8 + g]);
                b[nt][1] = __float_as_uint(Bb[(kb + t + 4) * GBP + wn + nt * 8 + g]);
            }
            #pragma unroll
            for (int mt = 0; mt < 2; mt++)
                #pragma unroll
                for (int nt = 0; nt < 8; nt++)
                    mma_tf32(c[mt][nt], a[mt], b[nt]);
        }
        __syncthreads();
    }

    #pragma unroll
    for (int mt = 0; mt < 2; mt++) {
        const int r = row0 + wm + mt * 16 + g;
        #pragma unroll
        for (int nt = 0; nt < 8; nt++) {
            const int cn = col0 + wn + nt * 8 + t * 2;
            const float b0 = bias[cn], b1 = bias[cn + 1];
            float2 v0 = make_float2(c[mt][nt][0] + b0, c[mt][nt][1] + b1);
            float2 v1 = make_float2(c[mt][nt][2] + b0, c[mt][nt][3] + b1);
            if (round_out) {
                v0.x = f2tf(v0.x); v0.y = f2tf(v0.y);
                v1.x = f2tf(v1.x); v1.y = f2tf(v1.y);
            }
            *(float2*)&C[(size_t)r * N + cn]       = v0;
            *(float2*)&C[(size_t)(r + 8) * N + cn] = v1;
        }
    }
}
#define GEMM_SMEM ((2 * 128 * GAP + 2 * 32 * GBP) * (int)sizeof(float))  /* 71680 */

// ---------------------------------------------------------------------------
// Flash attention v4: 256-row Q tile, 8 warps x 32 q-rows (2 m-frags/warp).
// Every K/V B-fragment load feeds TWO mmas -> ~3.8 instrs/MMA vs 4.7 before.
//   QsPs[256][68]  Q staging then P tile (A-frag bank 4g+t, conflict-free)
//   Ks[2][64][68]  row-major K == col-major K^T for mma (bank 4g+t)
//   Vs[2][64][72]  (bank 8t+g)
// qkv is tf32-valued; no cvt in any inner loop. attn written tf32-rounded.
// ---------------------------------------------------------------------------
#define QT 256
#define FQP 68
#define FKP 68
#define FVP 72
#define FLASH_SMEM ((QT * FQP + 2 * 64 * FKP + 2 * 64 * FVP) * (int)sizeof(float)) /* 141312 */

__global__ __launch_bounds__(256) void flash_tf32_kernel(
    const float* __restrict__ qkv, float* __restrict__ attn)
{
    extern __shared__ float sm[];
    float* QsPs = sm;                         // 256*68
    float* Ks   = QsPs + QT * FQP;            // [2][64*68]
    float* Vs   = Ks + 2 * 64 * FKP;          // [2][64*72]

    const int bh = blockIdx.x;
    const int b = bh / NH, h = bh % NH;
    const int q0 = blockIdx.y * QT;
    const int tid = threadIdx.x;
    const int lane = tid & 31;
    const int wid = tid >> 5;
    const int g = lane >> 2, t = lane & 3;
    const int m0 = wid * 32;                  // warp owns q rows m0..m0+31

    const float scale = 0.125f;   // exact power of 2: q*scale stays tf32-valued
    const float* qbase = qkv + (size_t)b * SS * QKV_N + h * HS;
    const float* kbase = qbase + HIDDEN;
    const float* vbase = qbase + 2 * HIDDEN;

    auto load_kv = [&](int it, int buf) {
        const int k0 = it * 64;
        float* Kb = Ks + buf * (64 * FKP);
        float* Vb = Vs + buf * (64 * FVP);
        #pragma unroll
        for (int i = 0; i < 4; i++) {        // K: 64 rows x 16 chunks
            const int ch = tid + 256 * i;
            const int key = ch >> 4, sg = (ch & 15) * 4;
            cpa16(Kb + key * FKP + sg, &kbase[(size_t)(k0 + key) * QKV_N + sg]);
        }
        #pragma unroll
        for (int i = 0; i < 4; i++) {        // V
            const int ch = tid + 256 * i;
            const int key = ch >> 4, sg = (ch & 15) * 4;
            cpa16(Vb + key * FVP + sg, &vbase[(size_t)(k0 + key) * QKV_N + sg]);
        }
        cp_commit();
    };

    load_kv(0, 0);
    // Stage Q tile (256 x 64), scaled.
    #pragma unroll
    for (int i = 0; i < 16; i++) {
        const int e = tid + 256 * i;     // 0..4095
        const int r = e >> 4;            // 0..255
        const int dc = (e & 15) * 4;
        float4 q4 = *(const float4*)&qbase[(size_t)(q0 + r) * QKV_N + dc];
        q4.x *= scale; q4.y *= scale; q4.z *= scale; q4.w *= scale;
        *(float4*)&QsPs[r * FQP + dc] = q4;
    }
    __syncthreads();

    // Q fragments -> registers, both m-tiles (reused for all key tiles).
    unsigned qf[2][8][4];
    #pragma unroll
    for (int mt = 0; mt < 2; mt++) {
        const int mb = m0 + mt * 16;
        #pragma unroll
        for (int ks = 0; ks < 8; ks++) {
            const int kb = ks * 8;
            qf[mt][ks][0] = __float_as_uint(QsPs[(mb + g    ) * FQP + kb + t    ]);
            qf[mt][ks][1] = __float_as_uint(QsPs[(mb + g + 8) * FQP + kb + t    ]);
            qf[mt][ks][2] = __float_as_uint(QsPs[(mb + g    ) * FQP + kb + t + 4]);
            qf[mt][ks][3] = __float_as_uint(QsPs[(mb + g + 8) * FQP + kb + t + 4]);
        }
    }

    float o[2][8][4] = {};
    float mrow[2][2], lrow[2][2];
    #pragma unroll
    for (int mt = 0; mt < 2; mt++) { mrow[mt][0] = mrow[mt][1] = -1e30f; lrow[mt][0] = lrow[mt][1] = 0.f; }

    const int NT = SS / 64;
    for (int it = 0; it < NT; it++) {
        const int buf = it & 1;
        if (it + 1 < NT) { load_kv(it + 1, buf ^ 1); cp_wait1(); }
        else             { cp_wait0(); }
        __syncthreads();

        const float* Kb = Ks + buf * (64 * FKP);
        const float* Vb = Vs + buf * (64 * FVP);

        // ---- S = Q @ K^T, both m-tiles sharing each K fragment ----
        float s[2][8][4] = {};
        #pragma unroll
        for (int ks = 0; ks < 8; ks++) {
            const int kb = ks * 8;
            unsigned bfr[8][2];
            #pragma unroll
            for (int nt = 0; nt < 8; nt++) {
                bfr[nt][0] = __float_as_uint(Kb[(nt * 8 + g) * FKP + kb + t    ]);
                bfr[nt][1] = __float_as_uint(Kb[(nt * 8 + g) * FKP + kb + t + 4]);
            }
            #pragma unroll
            for (int nt = 0; nt < 8; nt++) {
                mma_tf32(s[0][nt], qf[0][ks], bfr[nt]);
                mma_tf32(s[1][nt], qf[1][ks], bfr[nt]);
            }
        }

        // ---- online softmax + P publish, per m-tile ----
        #pragma unroll
        for (int mt = 0; mt < 2; mt++) {
            float mx0 = -1e30f, mx1 = -1e30f;
            #pragma unroll
            for (int nt = 0; nt < 8; nt++) {
                mx0 = fmaxf(mx0, fmaxf(s[mt][nt][0], s[mt][nt][1]));
                mx1 = fmaxf(mx1, fmaxf(s[mt][nt][2], s[mt][nt][3]));
            }
            mx0 = fmaxf(mx0, __shfl_xor_sync(0xffffffffu, mx0, 1));
            mx0 = fmaxf(mx0, __shfl_xor_sync(0xffffffffu, mx0, 2));
            mx1 = fmaxf(mx1, __shfl_xor_sync(0xffffffffu, mx1, 1));
            mx1 = fmaxf(mx1, __shfl_xor_sync(0xffffffffu, mx1, 2));

            const float mn0 = fmaxf(mrow[mt][0], mx0);
            const float mn1 = fmaxf(mrow[mt][1], mx1);
            const float al0 = __expf(mrow[mt][0] - mn0);
            const float al1 = __expf(mrow[mt][1] - mn1);
            mrow[mt][0] = mn0; mrow[mt][1] = mn1;

            float sum0 = 0.f, sum1 = 0.f;
            #pragma unroll
            for (int nt = 0; nt < 8; nt++) {
                s[mt][nt][0] = __expf(s[mt][nt][0] - mn0); sum0 += s[mt][nt][0];
                s[mt][nt][1] = __expf(s[mt][nt][1] - mn0); sum0 += s[mt][nt][1];
                s[mt][nt][2] = __expf(s[mt][nt][2] - mn1); sum1 += s[mt][nt][2];
                s[mt][nt][3] = __expf(s[mt][nt][3] - mn1); sum1 += s[mt][nt][3];
            }
            sum0 += __shfl_xor_sync(0xffffffffu, sum0, 1);
            sum0 += __shfl_xor_sync(0xffffffffu, sum0, 2);
            sum1 += __shfl_xor_sync(0xffffffffu, sum1, 1);
            sum1 += __shfl_xor_sync(0xffffffffu, sum1, 2);
            lrow[mt][0] = lrow[mt][0] * al0 + sum0;
            lrow[mt][1] = lrow[mt][1] * al1 + sum1;

            #pragma unroll
            for (int nt = 0; nt < 8; nt++) {
                o[mt][nt][0] *= al0; o[mt][nt][1] *= al0;
                o[mt][nt][2] *= al1; o[mt][nt][3] *= al1;
            }

            const int mb = m0 + mt * 16;
            #pragma unroll
            for (int nt = 0; nt < 8; nt++) {
                const int cc = nt * 8 + t * 2;
                QsPs[(mb + g    ) * FQP + cc    ] = f2tf(s[mt][nt][0]);
                QsPs[(mb + g    ) * FQP + cc + 1] = f2tf(s[mt][nt][1]);
                QsPs[(mb + g + 8) * FQP + cc    ] = f2tf(s[mt][nt][2]);
                QsPs[(mb + g + 8) * FQP + cc + 1] = f2tf(s[mt][nt][3]);
            }
        }
        __syncwarp();

        // ---- O += P @ V, both m-tiles sharing each V fragment ----
        #pragma unroll
        for (int ks = 0; ks < 8; ks++) {
            const int kb = ks * 8;
            unsigned bfr[8][2], a0[4], a1[4];
            #pragma unroll
            for (int nt = 0; nt < 8; nt++) {
                bfr[nt][0] = __float_as_uint(Vb[(kb + t    ) * FVP + nt * 8 + g]);
                bfr[nt][1] = __float_as_uint(Vb[(kb + t + 4) * FVP + nt * 8 + g]);
            }
            a0[0] = __float_as_uint(QsPs[(m0 + g     ) * FQP + kb + t    ]);
            a0[1] = __float_as_uint(QsPs[(m0 + g +  8) * FQP + kb + t    ]);
            a0[2] = __float_as_uint(QsPs[(m0 + g     ) * FQP + kb + t + 4]);
            a0[3] = __float_as_uint(QsPs[(m0 + g +  8) * FQP + kb + t + 4]);
            a1[0] = __float_as_uint(QsPs[(m0 + g + 16) * FQP + kb + t    ]);
            a1[1] = __float_as_uint(QsPs[(m0 + g + 24) * FQP + kb + t    ]);
            a1[2] = __float_as_uint(QsPs[(m0 + g + 16) * FQP + kb + t + 4]);
            a1[3] = __float_as_uint(QsPs[(m0 + g + 24) * FQP + kb + t + 4]);
            #pragma unroll
            for (int nt = 0; nt < 8; nt++) {
                mma_tf32(o[0][nt], a0, bfr[nt]);
                mma_tf32(o[1][nt], a1, bfr[nt]);
            }
        }
        __syncthreads();   // all warps done with Kb/Vb before next-next tile lands
    }

    // normalize + store (tf32-rounded: consumed by tf32 out-proj A operand)
    #pragma unroll
    for (int mt = 0; mt < 2; mt++) {
        const float inv0 = 1.f / lrow[mt][0];
        const float inv1 = 1.f / lrow[mt][1];
        const int qr0 = q0 + m0 + mt * 16 + g;
        #pragma unroll
        for (int nt = 0; nt < 8; nt++) {
            const int d = h * HS + nt * 8 + t * 2;
            float2 v0 = make_float2(f2tf(o[mt][nt][0] * inv0), f2tf(o[mt][nt][1] * inv0));
            float2 v1 = make_float2(f2tf(o[mt][nt][2] * inv1), f2tf(o[mt][nt][3] * inv1));
            *(float2*)&attn[((size_t)b * SS + qr0    ) * HIDDEN + d] = v0;
            *(float2*)&attn[((size_t)b * SS + qr0 + 8) * HIDDEN + d] = v1;
        }
    }
}

// ---------------------------------------------------------------------------
extern "C" void kernel_launch(void* const* d_in, const int* in_sizes, int n_in,
                              void* d_out, int out_size)
{
    (void)in_sizes; (void)n_in; (void)out_size;
    const float* x    = (const float*)d_in[0];
    const float* Wqkv = (const float*)d_in[1];
    const float* bqkv = (const float*)d_in[2];
    const float* Wo   = (const float*)d_in[3];
    const float* bo   = (const float*)d_in[4];
    float* out = (float*)d_out;

    float *qkv_buf, *attn_buf, *x_tf, *wqkv_tf, *wo_tf;
    cudaGetSymbolAddress((void**)&qkv_buf, g_qkv);
    cudaGetSymbolAddress((void**)&attn_buf, g_attn);
    cudaGetSymbolAddress((void**)&x_tf, g_x_tf);
    cudaGetSymbolAddress((void**)&wqkv_tf, g_wqkv_tf);
    cudaGetSymbolAddress((void**)&wo_tf, g_wo_tf);

    cudaFuncSetAttribute(gemm_tf32_kernel,
                         cudaFuncAttributeMaxDynamicSharedMemorySize, GEMM_SMEM);
    cudaFuncSetAttribute(flash_tf32_kernel,
                         cudaFuncAttributeMaxDynamicSharedMemorySize, FLASH_SMEM);

    // 0) tf32-round inputs once (x, Wqkv, Wo)
    {
        const int nx = M_TOT * HIDDEN / 4;
        tf32_prep_kernel<<<(nx + 255) / 256, 256>>>((const float4*)x, (float4*)x_tf, nx);
        const int nw = HIDDEN * QKV_N / 4;
        tf32_prep_kernel<<<(nw + 255) / 256, 256>>>((const float4*)Wqkv, (float4*)wqkv_tf, nw);
        const int no = HIDDEN * HIDDEN / 4;
        tf32_prep_kernel<<<(no + 255) / 256, 256>>>((const float4*)Wo, (float4*)wo_tf, no);
    }
    // 1) QKV projection (output rounded for flash)
    {
        dim3 grid(QKV_N / 128, M_TOT / 128);   // (24, 32)
        gemm_tf32_kernel<<<grid, 256, GEMM_SMEM>>>(x_tf, wqkv_tf, bqkv, qkv_buf,
                                                   M_TOT, QKV_N, HIDDEN, 1);
    }
    // 2) Flash attention (output rounded for out-proj)
    {
        dim3 grid(BB * NH, SS / QT);           // (32, 8)
        flash_tf32_kernel<<<grid, 256, FLASH_SMEM>>>(qkv_buf, attn_buf);
    }
    // 3) Output projection (final output, unrounded)
    {
        dim3 grid(HIDDEN / 128, M_TOT / 128);  // (8, 32)
        gemm_tf32_kernel<<<grid, 256, GEMM_SMEM>>>(attn_buf, wo_tf, bo, out,
                                                   M_TOT, HIDDEN, HIDDEN, 0);
    }
}

// round 14
// speedup vs baseline: 6.3992x; 1.6842x over previous
#include <cuda_runtime.h>
#include <cuda_fp16.h>
#include <cstdint>

#define HIDDEN 1024
#define NH 16
#define HS 64
#define BB 2
#define SS 2048
#define M_TOT (BB*SS)       /* 4096 */
#define QKV_N (3*HIDDEN)    /* 3072 */

// Packed-half2 buffers (uint = 2 fp16). No runtime allocation.
__device__ unsigned g_xp   [(size_t)M_TOT * (HIDDEN/2)];       // 8 MB
__device__ unsigned g_wqkvp[(size_t)(HIDDEN/2) * QKV_N];       // 6 MB
__device__ unsigned g_wop  [(size_t)(HIDDEN/2) * HIDDEN];      // 2 MB
__device__ unsigned g_qkvp [(size_t)M_TOT * (QKV_N/2)];        // 25 MB
__device__ unsigned g_attnp[(size_t)M_TOT * (HIDDEN/2)];       // 8 MB
__device__ unsigned g_vtp  [(size_t)BB*NH * HS * (SS/2)];      // 8 MB

// ---------------------------------------------------------------------------
// Helpers
// ---------------------------------------------------------------------------
__device__ __forceinline__ unsigned pack2(float a, float b) {
    __half2 h = __floats2half2_rn(a, b);
    return *(unsigned*)&h;
}

__device__ __forceinline__ void mma_f16(float* c, const unsigned* a, const unsigned* b) {
    asm volatile(
        "mma.sync.aligned.m16n8k16.row.col.f32.f16.f16.f32 "
        "{%0,%1,%2,%3}, {%4,%5,%6,%7}, {%8,%9}, {%0,%1,%2,%3};\n"
        : "+f"(c[0]), "+f"(c[1]), "+f"(c[2]), "+f"(c[3])
        : "r"(a[0]), "r"(a[1]), "r"(a[2]), "r"(a[3]),
          "r"(b[0]), "r"(b[1]));
}

__device__ __forceinline__ void cpa16(unsigned* dst, const unsigned* src) {
    unsigned d = (unsigned)__cvta_generic_to_shared(dst);
    asm volatile("cp.async.cg.shared.global [%0], [%1], 16;\n" :: "r"(d), "l"(src));
}
__device__ __forceinline__ void cp_commit() { asm volatile("cp.async.commit_group;\n"); }
__device__ __forceinline__ void cp_wait1() { asm volatile("cp.async.wait_group 1;\n" ::: "memory"); }
__device__ __forceinline__ void cp_wait0() { asm volatile("cp.async.wait_group 0;\n" ::: "memory"); }

// ---------------------------------------------------------------------------
// Prep: fp32 -> packed half2 (k-contiguous pairs).
// ---------------------------------------------------------------------------
__global__ __launch_bounds__(256) void prep_x_kernel(
    const float2* __restrict__ in, unsigned* __restrict__ out, int n2)
{
    const int i = blockIdx.x * blockDim.x + threadIdx.x;
    if (i < n2) { float2 v = in[i]; out[i] = pack2(v.x, v.y); }
}

// W[K][N] fp32 -> Wp[kk][n] = half2(W[2kk][n], W[2kk+1][n])
__global__ __launch_bounds__(256) void prep_w_kernel(
    const float* __restrict__ W, unsigned* __restrict__ Wp, int N, int total)
{
    const int i = blockIdx.x * blockDim.x + threadIdx.x;
    if (i < total) {
        const int kk = i / N, n = i - kk * N;
        Wp[i] = pack2(W[(size_t)(2 * kk) * N + n], W[(size_t)(2 * kk + 1) * N + n]);
    }
}

// Build Vt[bh][d][kk] = half2(V[2kk][d], V[2kk+1][d]) from packed qkv.
// Block: one (bh, 64-token tile). smem transpose.
__global__ __launch_bounds__(256) void pack_vt_kernel(
    const unsigned* __restrict__ qkvp, unsigned* __restrict__ vtp)
{
    __shared__ unsigned Ts[64][33];
    const int bh = blockIdx.y;            // 0..31
    const int b = bh / NH, h = bh % NH;
    const int t0 = blockIdx.x * 64;       // token tile base
    const int tid = threadIdx.x;

    // Load 64 tokens x 32 feature-uints (coalesced along features).
    #pragma unroll
    for (int i = 0; i < 8; i++) {
        const int e = tid + 256 * i;      // 0..2047
        const int tr = e >> 5, dq = e & 31;
        Ts[tr][dq] = qkvp[(size_t)(b * SS + t0 + tr) * (QKV_N/2) + (2*HIDDEN)/2 + h * 32 + dq];
    }
    __syncthreads();

    // Emit 64 d-rows x 32 kk (coalesced along kk).
    const size_t vbase = (size_t)bh * HS * (SS/2);
    #pragma unroll
    for (int i = 0; i < 8; i++) {
        const int e = tid + 256 * i;
        const int d = e >> 5, kk = e & 31;
        const int dq = d >> 1, sel = d & 1;
        const unsigned u0 = Ts[2 * kk][dq];
        const unsigned u1 = Ts[2 * kk + 1][dq];
        const unsigned out = sel ? __byte_perm(u0, u1, 0x7632)
                                 : __byte_perm(u0, u1, 0x5410);
        vtp[vbase + (size_t)d * (SS/2) + (t0 >> 1) + kk] = out;
    }
}

// ---------------------------------------------------------------------------
// FP16 GEMM, cp.async double-buffered: C[M,N] = A[M,K] @ B[K,N] + bias[N]
// Ap packed [m][kk], Bp packed [kk][n]. fp16_out: C as packed half2.
// As [m][pitch 20 uints] (bank 4g+t), Bs [kk][pitch 136] (bank 8t+g).
// ---------------------------------------------------------------------------
#define GAP 20
#define GBP 136
#define GEMM_SMEM ((2 * 128 * GAP + 2 * 16 * GBP) * (int)sizeof(unsigned)) /* 37888 */

__global__ __launch_bounds__(256, 2) void gemm_f16_kernel(
    const unsigned* __restrict__ Ap, const unsigned* __restrict__ Bp,
    const float* __restrict__ bias, void* __restrict__ Cout,
    int M, int N, int K, int fp16_out)
{
    extern __shared__ unsigned smu[];
    unsigned* As = smu;                        // [2][128*20]
    unsigned* Bs = smu + 2 * 128 * GAP;        // [2][16*136]

    const int tid  = threadIdx.x;
    const int lane = tid & 31;
    const int wid  = tid >> 5;
    const int g = lane >> 2, t = lane & 3;
    const int wm = (wid & 3) * 32;
    const int wn = (wid >> 2) * 64;
    const int row0 = blockIdx.y * 128;
    const int col0 = blockIdx.x * 128;
    const int Kp = K / 2;                      // packed row length

    float c[2][8][4] = {};
    const int NIT = K / 32;

    auto load_tile = [&](int it, int buf) {
        const int kk0 = it * 16;
        unsigned* Ab = As + buf * (128 * GAP);
        unsigned* Bb = Bs + buf * (16 * GBP);
        #pragma unroll
        for (int i = 0; i < 2; i++) {          // A: 128 rows x 4 chunks(16B)
            const int ch = tid + 256 * i;      // 0..511
            const int r = ch >> 2, c4 = (ch & 3) * 4;
            cpa16(Ab + r * GAP + c4, Ap + (size_t)(row0 + r) * Kp + kk0 + c4);
        }
        #pragma unroll
        for (int i = 0; i < 2; i++) {          // B: 16 kk-rows x 32 chunks
            const int ch = tid + 256 * i;
            const int r = ch >> 5, c4 = (ch & 31) * 4;
            cpa16(Bb + r * GBP + c4, Bp + (size_t)(kk0 + r) * N + col0 + c4);
        }
        cp_commit();
    };

    load_tile(0, 0);
    for (int it = 0; it < NIT; it++) {
        const int buf = it & 1;
        if (it + 1 < NIT) { load_tile(it + 1, buf ^ 1); cp_wait1(); }
        else              { cp_wait0(); }
        __syncthreads();

        const unsigned* Ab = As + buf * (128 * GAP);
        const unsigned* Bb = Bs + buf * (16 * GBP);
        #pragma unroll
        for (int ks = 0; ks < 2; ks++) {       // 2 k16 steps per BK=32
            const int kb = ks * 8;             // kk units
            unsigned a[2][4], b[8][2];
            #pragma unroll
            for (int mt = 0; mt < 2; mt++) {
                const int mb = wm + mt * 16;
                a[mt][0] = Ab[(mb + g    ) * GAP + kb + t    ];
                a[mt][1] = Ab[(mb + g + 8) * GAP + kb + t    ];
                a[mt][2] = Ab[(mb + g    ) * GAP + kb + t + 4];
                a[mt][3] = Ab[(mb + g + 8) * GAP + kb + t + 4];
            }
            #pragma unroll
            for (int nt = 0; nt < 8; nt++) {
                b[nt][0] = Bb[(kb + t    ) * GBP + wn + nt * 8 + g];
                b[nt][1] = Bb[(kb + t + 4) * GBP + wn + nt * 8 + g];
            }
            #pragma unroll
            for (int mt = 0; mt < 2; mt++)
                #pragma unroll
                for (int nt = 0; nt < 8; nt++)
                    mma_f16(c[mt][nt], a[mt], b[nt]);
        }
        __syncthreads();
    }

    #pragma unroll
    for (int mt = 0; mt < 2; mt++) {
        const int r = row0 + wm + mt * 16 + g;
        #pragma unroll
        for (int nt = 0; nt < 8; nt++) {
            const int cn = col0 + wn + nt * 8 + t * 2;
            const float b0 = bias[cn], b1 = bias[cn + 1];
            const float v00 = c[mt][nt][0] + b0, v01 = c[mt][nt][1] + b1;
            const float v10 = c[mt][nt][2] + b0, v11 = c[mt][nt][3] + b1;
            if (fp16_out) {
                unsigned* Cp = (unsigned*)Cout;
                Cp[(size_t)r       * (N/2) + (cn >> 1)] = pack2(v00, v01);
                Cp[(size_t)(r + 8) * (N/2) + (cn >> 1)] = pack2(v10, v11);
            } else {
                float* C = (float*)Cout;
                *(float2*)&C[(size_t)r       * N + cn] = make_float2(v00, v01);
                *(float2*)&C[(size_t)(r + 8) * N + cn] = make_float2(v10, v11);
            }
        }
    }
}

// ---------------------------------------------------------------------------
// Flash attention fp16: 256-row Q tile, 8 warps x 32 q-rows, k16 mma.
//   QsPs[256][36u]  Q (packed dd) then P (packed key-pairs); bank 4g+t
//   Ks[2][64][36u]  K rows packed dd (row-major K == col-major K^T); bank 4g+t
//   Vs[2][64][36u]  Vt rows: [d][key-pair]; bank 4g+t
// ---------------------------------------------------------------------------
#define QT 256
#define FP 36
#define FLASH_SMEM ((QT * FP + 2 * 64 * FP + 2 * 64 * FP) * (int)sizeof(unsigned)) /* 73728 */

__global__ __launch_bounds__(256) void flash_f16_kernel(
    const unsigned* __restrict__ qkvp, const unsigned* __restrict__ vtp,
    unsigned* __restrict__ attnp)
{
    extern __shared__ unsigned smu[];
    unsigned* QsPs = smu;                      // 256*36
    unsigned* Ks   = QsPs + QT * FP;           // [2][64*36]
    unsigned* Vs   = Ks + 2 * 64 * FP;         // [2][64*36]

    const int bh = blockIdx.x;
    const int b = bh / NH, h = bh % NH;
    const int q0 = blockIdx.y * QT;
    const int tid = threadIdx.x;
    const int lane = tid & 31;
    const int wid = tid >> 5;
    const int g = lane >> 2, t = lane & 3;
    const int m0 = wid * 32;

    const int QROW = QKV_N / 2;                // 1536 uints per token
    const unsigned* qcol = qkvp + h * 32;                    // Q features
    const unsigned* kcol = qkvp + HIDDEN/2 + h * 32;         // K features
    const unsigned* vtb  = vtp + (size_t)bh * HS * (SS/2);

    auto load_kv = [&](int it, int buf) {
        const int k0 = it * 64;
        unsigned* Kb = Ks + buf * (64 * FP);
        unsigned* Vb = Vs + buf * (64 * FP);
        #pragma unroll
        for (int i = 0; i < 2; i++) {          // K: 64 rows x 8 chunks
            const int ch = tid + 256 * i;      // 0..511
            const int key = ch >> 3, c4 = (ch & 7) * 4;
            cpa16(Kb + key * FP + c4, kcol + (size_t)(b * SS + k0 + key) * QROW + c4);
        }
        #pragma unroll
        for (int i = 0; i < 2; i++) {          // Vt: 64 d-rows x 8 chunks
            const int ch = tid + 256 * i;
            const int d = ch >> 3, c4 = (ch & 7) * 4;
            cpa16(Vb + d * FP + c4, vtb + (size_t)d * (SS/2) + (k0 >> 1) + c4);
        }
        cp_commit();
    };

    load_kv(0, 0);
    // Stage Q tile (256 x 32 uints), scaled by 0.125 (exact p2 in fp16).
    const __half2 sc2 = __float2half2_rn(0.125f);
    #pragma unroll
    for (int i = 0; i < 8; i++) {
        const int e = tid + 256 * i;           // 0..2047
        const int r = e >> 3, c4 = (e & 7) * 4;
        uint4 u = *(const uint4*)(qcol + (size_t)(b * SS + q0 + r) * QROW + c4);
        __half2 h0 = __hmul2(*(__half2*)&u.x, sc2);
        __half2 h1 = __hmul2(*(__half2*)&u.y, sc2);
        __half2 h2 = __hmul2(*(__half2*)&u.z, sc2);
        __half2 h3 = __hmul2(*(__half2*)&u.w, sc2);
        u.x = *(unsigned*)&h0; u.y = *(unsigned*)&h1;
        u.z = *(unsigned*)&h2; u.w = *(unsigned*)&h3;
        *(uint4*)(QsPs + r * FP + c4) = u;
    }
    __syncthreads();

    // Q fragments -> registers (4 k16 steps over d=64).
    unsigned qf[2][4][4];
    #pragma unroll
    for (int mt = 0; mt < 2; mt++) {
        const int mb = m0 + mt * 16;
        #pragma unroll
        for (int ks = 0; ks < 4; ks++) {
            const int kb = ks * 8;
            qf[mt][ks][0] = QsPs[(mb + g    ) * FP + kb + t    ];
            qf[mt][ks][1] = QsPs[(mb + g + 8) * FP + kb + t    ];
            qf[mt][ks][2] = QsPs[(mb + g    ) * FP + kb + t + 4];
            qf[mt][ks][3] = QsPs[(mb + g + 8) * FP + kb + t + 4];
        }
    }

    float o[2][8][4] = {};
    float mrow[2][2], lrow[2][2];
    #pragma unroll
    for (int mt = 0; mt < 2; mt++) { mrow[mt][0] = mrow[mt][1] = -1e30f; lrow[mt][0] = lrow[mt][1] = 0.f; }

    const int NT = SS / 64;
    for (int it = 0; it < NT; it++) {
        const int buf = it & 1;
        if (it + 1 < NT) { load_kv(it + 1, buf ^ 1); cp_wait1(); }
        else             { cp_wait0(); }
        __syncthreads();

        const unsigned* Kb = Ks + buf * (64 * FP);
        const unsigned* Vb = Vs + buf * (64 * FP);

        // ---- S = Q @ K^T (4 k16 steps) ----
        float s[2][8][4] = {};
        #pragma unroll
        for (int ks = 0; ks < 4; ks++) {
            const int kb = ks * 8;
            unsigned bfr[8][2];
            #pragma unroll
            for (int nt = 0; nt < 8; nt++) {
                bfr[nt][0] = Kb[(nt * 8 + g) * FP + kb + t    ];
                bfr[nt][1] = Kb[(nt * 8 + g) * FP + kb + t + 4];
            }
            #pragma unroll
            for (int nt = 0; nt < 8; nt++) {
                mma_f16(s[0][nt], qf[0][ks], bfr[nt]);
                mma_f16(s[1][nt], qf[1][ks], bfr[nt]);
            }
        }

        // ---- online softmax + P publish (packed key-pairs) ----
        #pragma unroll
        for (int mt = 0; mt < 2; mt++) {
            float mx0 = -1e30f, mx1 = -1e30f;
            #pragma unroll
            for (int nt = 0; nt < 8; nt++) {
                mx0 = fmaxf(mx0, fmaxf(s[mt][nt][0], s[mt][nt][1]));
                mx1 = fmaxf(mx1, fmaxf(s[mt][nt][2], s[mt][nt][3]));
            }
            mx0 = fmaxf(mx0, __shfl_xor_sync(0xffffffffu, mx0, 1));
            mx0 = fmaxf(mx0, __shfl_xor_sync(0xffffffffu, mx0, 2));
            mx1 = fmaxf(mx1, __shfl_xor_sync(0xffffffffu, mx1, 1));
            mx1 = fmaxf(mx1, __shfl_xor_sync(0xffffffffu, mx1, 2));

            const float mn0 = fmaxf(mrow[mt][0], mx0);
            const float mn1 = fmaxf(mrow[mt][1], mx1);
            const float al0 = __expf(mrow[mt][0] - mn0);
            const float al1 = __expf(mrow[mt][1] - mn1);
            mrow[mt][0] = mn0; mrow[mt][1] = mn1;

            float sum0 = 0.f, sum1 = 0.f;
            #pragma unroll
            for (int nt = 0; nt < 8; nt++) {
                s[mt][nt][0] = __expf(s[mt][nt][0] - mn0); sum0 += s[mt][nt][0];
                s[mt][nt][1] = __expf(s[mt][nt][1] - mn0); sum0 += s[mt][nt][1];
                s[mt][nt][2] = __expf(s[mt][nt][2] - mn1); sum1 += s[mt][nt][2];
                s[mt][nt][3] = __expf(s[mt][nt][3] - mn1); sum1 += s[mt][nt][3];
            }
            sum0 += __shfl_xor_sync(0xffffffffu, sum0, 1);
            sum0 += __shfl_xor_sync(0xffffffffu, sum0, 2);
            sum1 += __shfl_xor_sync(0xffffffffu, sum1, 1);
            sum1 += __shfl_xor_sync(0xffffffffu, sum1, 2);
            lrow[mt][0] = lrow[mt][0] * al0 + sum0;
            lrow[mt][1] = lrow[mt][1] * al1 + sum1;

            #pragma unroll
            for (int nt = 0; nt < 8; nt++) {
                o[mt][nt][0] *= al0; o[mt][nt][1] *= al0;
                o[mt][nt][2] *= al1; o[mt][nt][3] *= al1;
            }

            const int mb = m0 + mt * 16;
            #pragma unroll
            for (int nt = 0; nt < 8; nt++) {
                QsPs[(mb + g    ) * FP + nt * 4 + t] = pack2(s[mt][nt][0], s[mt][nt][1]);
                QsPs[(mb + g + 8) * FP + nt * 4 + t] = pack2(s[mt][nt][2], s[mt][nt][3]);
            }
        }
        __syncwarp();

        // ---- O += P @ V (4 k16 steps over 64 keys) ----
        #pragma unroll
        for (int ks = 0; ks < 4; ks++) {
            const int kb = ks * 8;               // kk units
            unsigned bfr[8][2], a0[4], a1[4];
            #pragma unroll
            for (int nt = 0; nt < 8; nt++) {
                bfr[nt][0] = Vb[(nt * 8 + g) * FP + kb + t    ];
                bfr[nt][1] = Vb[(nt * 8 + g) * FP + kb + t + 4];
            }
            a0[0] = QsPs[(m0 + g     ) * FP + kb + t    ];
            a0[1] = QsPs[(m0 + g +  8) * FP + kb + t    ];
            a0[2] = QsPs[(m0 + g     ) * FP + kb + t + 4];
            a0[3] = QsPs[(m0 + g +  8) * FP + kb + t + 4];
            a1[0] = QsPs[(m0 + g + 16) * FP + kb + t    ];
            a1[1] = QsPs[(m0 + g + 24) * FP + kb + t    ];
            a1[2] = QsPs[(m0 + g + 16) * FP + kb + t + 4];
            a1[3] = QsPs[(m0 + g + 24) * FP + kb + t + 4];
            #pragma unroll
            for (int nt = 0; nt < 8; nt++) {
                mma_f16(o[0][nt], a0, bfr[nt]);
                mma_f16(o[1][nt], a1, bfr[nt]);
            }
        }
        __syncthreads();
    }

    // normalize + store packed fp16 (consumed by fp16 out-proj)
    #pragma unroll
    for (int mt = 0; mt < 2; mt++) {
        const float inv0 = 1.f / lrow[mt][0];
        const float inv1 = 1.f / lrow[mt][1];
        const int qr0 = q0 + m0 + mt * 16 + g;
        #pragma unroll
        for (int nt = 0; nt < 8; nt++) {
            const int cc = h * 32 + nt * 4 + t;   // packed d index
            attnp[(size_t)(b * SS + qr0    ) * (HIDDEN/2) + cc] =
                pack2(o[mt][nt][0] * inv0, o[mt][nt][1] * inv0);
            attnp[(size_t)(b * SS + qr0 + 8) * (HIDDEN/2) + cc] =
                pack2(o[mt][nt][2] * inv1, o[mt][nt][3] * inv1);
        }
    }
}

// ---------------------------------------------------------------------------
extern "C" void kernel_launch(void* const* d_in, const int* in_sizes, int n_in,
                              void* d_out, int out_size)
{
    (void)in_sizes; (void)n_in; (void)out_size;
    const float* x    = (const float*)d_in[0];
    const float* Wqkv = (const float*)d_in[1];
    const float* bqkv = (const float*)d_in[2];
    const float* Wo   = (const float*)d_in[3];
    const float* bo   = (const float*)d_in[4];
    float* out = (float*)d_out;

    unsigned *xp, *wqkvp, *wop, *qkvp, *attnp, *vtp;
    cudaGetSymbolAddress((void**)&xp, g_xp);
    cudaGetSymbolAddress((void**)&wqkvp, g_wqkvp);
    cudaGetSymbolAddress((void**)&wop, g_wop);
    cudaGetSymbolAddress((void**)&qkvp, g_qkvp);
    cudaGetSymbolAddress((void**)&attnp, g_attnp);
    cudaGetSymbolAddress((void**)&vtp, g_vtp);

    cudaFuncSetAttribute(gemm_f16_kernel,
                         cudaFuncAttributeMaxDynamicSharedMemorySize, GEMM_SMEM);
    cudaFuncSetAttribute(flash_f16_kernel,
                         cudaFuncAttributeMaxDynamicSharedMemorySize, FLASH_SMEM);

    // 0) pack inputs to fp16
    {
        const int nx = M_TOT * HIDDEN / 2;
        prep_x_kernel<<<(nx + 255) / 256, 256>>>((const float2*)x, xp, nx);
        const int nw = (HIDDEN / 2) * QKV_N;
        prep_w_kernel<<<(nw + 255) / 256, 256>>>(Wqkv, wqkvp, QKV_N, nw);
        const int no = (HIDDEN / 2) * HIDDEN;
        prep_w_kernel<<<(no + 255) / 256, 256>>>(Wo, wop, HIDDEN, no);
    }
    // 1) QKV projection -> packed fp16 qkv
    {
        dim3 grid(QKV_N / 128, M_TOT / 128);   // (24, 32)
        gemm_f16_kernel<<<grid, 256, GEMM_SMEM>>>(xp, wqkvp, bqkv, qkvp,
                                                  M_TOT, QKV_N, HIDDEN, 1);
    }
    // 1b) pack V transposed (key-pairs) for PV mma
    {
        dim3 grid(SS / 64, BB * NH);           // (32, 32)
        pack_vt_kernel<<<grid, 256>>>(qkvp, vtp);
    }
    // 2) Flash attention -> packed fp16 attn
    {
        dim3 grid(BB * NH, SS / QT);           // (32, 8)
        flash_f16_kernel<<<grid, 256, FLASH_SMEM>>>(qkvp, vtp, attnp);
    }
    // 3) Output projection -> fp32 out
    {
        dim3 grid(HIDDEN / 128, M_TOT / 128);  // (8, 32)
        gemm_f16_kernel<<<grid, 256, GEMM_SMEM>>>(attnp, wop, bo, out,
                                                  M_TOT, HIDDEN, HIDDEN, 0);
    }
}

// round 17
// speedup vs baseline: 6.5323x; 1.0208x over previous
#include <cuda_runtime.h>
#include <cuda_fp16.h>
#include <cstdint>

#define HIDDEN 1024
#define NH 16
#define HS 64
#define BB 2
#define SS 2048
#define M_TOT (BB*SS)       /* 4096 */
#define QKV_N (3*HIDDEN)    /* 3072 */

// Packed-half2 buffers (uint = 2 fp16). No runtime allocation.
__device__ unsigned g_xp   [(size_t)M_TOT * (HIDDEN/2)];       // 8 MB
__device__ unsigned g_wqkvp[(size_t)(HIDDEN/2) * QKV_N];       // 6 MB  [kk][n]
__device__ unsigned g_wop  [(size_t)(HIDDEN/2) * HIDDEN];      // 2 MB  [kk][n]
__device__ unsigned g_qkvp [(size_t)M_TOT * (QKV_N/2)];        // 25 MB
__device__ unsigned g_attnp[(size_t)M_TOT * (HIDDEN/2)];       // 8 MB
__device__ unsigned g_vtp  [(size_t)BB*NH * HS * (SS/2)];      // 8 MB

// ---------------------------------------------------------------------------
// Helpers
// ---------------------------------------------------------------------------
__device__ __forceinline__ unsigned pack2(float a, float b) {
    __half2 h = __floats2half2_rn(a, b);
    return *(unsigned*)&h;
}

__device__ __forceinline__ void mma_f16(float* c, const unsigned* a, const unsigned* b) {
    asm volatile(
        "mma.sync.aligned.m16n8k16.row.col.f32.f16.f16.f32 "
        "{%0,%1,%2,%3}, {%4,%5,%6,%7}, {%8,%9}, {%0,%1,%2,%3};\n"
        : "+f"(c[0]), "+f"(c[1]), "+f"(c[2]), "+f"(c[3])
        : "r"(a[0]), "r"(a[1]), "r"(a[2]), "r"(a[3]),
          "r"(b[0]), "r"(b[1]));
}

__device__ __forceinline__ void cpa16(unsigned* dst, const unsigned* src) {
    unsigned d = (unsigned)__cvta_generic_to_shared(dst);
    asm volatile("cp.async.cg.shared.global [%0], [%1], 16;\n" :: "r"(d), "l"(src));
}
__device__ __forceinline__ void cp_commit() { asm volatile("cp.async.commit_group;\n"); }
__device__ __forceinline__ void cp_wait1() { asm volatile("cp.async.wait_group 1;\n" ::: "memory"); }
__device__ __forceinline__ void cp_wait0() { asm volatile("cp.async.wait_group 0;\n" ::: "memory"); }

// ---------------------------------------------------------------------------
// Prep kernels (fp32 -> packed half2)
// ---------------------------------------------------------------------------
__global__ __launch_bounds__(256) void prep_x_kernel(
    const float2* __restrict__ in, unsigned* __restrict__ out, int n2)
{
    const int i = blockIdx.x * blockDim.x + threadIdx.x;
    if (i < n2) { float2 v = in[i]; out[i] = pack2(v.x, v.y); }
}

// W[K][N] fp32 -> Wp[kk][n] = half2(W[2kk][n], W[2kk+1][n])
__global__ __launch_bounds__(256) void prep_w_kernel(
    const float* __restrict__ W, unsigned* __restrict__ Wp, int N, int total)
{
    const int i = blockIdx.x * blockDim.x + threadIdx.x;
    if (i < total) {
        const int kk = i / N, n = i - kk * N;
        Wp[i] = pack2(W[(size_t)(2 * kk) * N + n], W[(size_t)(2 * kk + 1) * N + n]);
    }
}

// Build Vt[bh][d][kk] = half2(V[2kk][d], V[2kk+1][d]) from packed qkv.
__global__ __launch_bounds__(256) void pack_vt_kernel(
    const unsigned* __restrict__ qkvp, unsigned* __restrict__ vtp)
{
    __shared__ unsigned Ts[64][33];
    const int bh = blockIdx.y;
    const int b = bh / NH, h = bh % NH;
    const int t0 = blockIdx.x * 64;
    const int tid = threadIdx.x;

    #pragma unroll
    for (int i = 0; i < 8; i++) {
        const int e = tid + 256 * i;
        const int tr = e >> 5, dq = e & 31;
        Ts[tr][dq] = qkvp[(size_t)(b * SS + t0 + tr) * (QKV_N/2) + HIDDEN + h * 32 + dq];
    }
    __syncthreads();

    const size_t vbase = (size_t)bh * HS * (SS/2);
    #pragma unroll
    for (int i = 0; i < 8; i++) {
        const int e = tid + 256 * i;
        const int d = e >> 5, kk = e & 31;
        const int dq = d >> 1, sel = d & 1;
        const unsigned u0 = Ts[2 * kk][dq];
        const unsigned u1 = Ts[2 * kk + 1][dq];
        const unsigned out = sel ? __byte_perm(u0, u1, 0x7632)
                                 : __byte_perm(u0, u1, 0x5410);
        vtp[vbase + (size_t)d * (SS/2) + (t0 >> 1) + kk] = out;
    }
}

// ---------------------------------------------------------------------------
// FP16 GEMM, BK=64, cp.async double-buffered: C = A @ B + bias.
// Ap packed [m][kk], Bp packed [kk][n].
// As [m][36u] (A-frag bank 4g+t+kb), Bs [kk][136u] (B-frag bank 8t+g).
// Halved sync count vs BK=32; identical MMA accumulation order (bit-exact).
// ---------------------------------------------------------------------------
#define GAP 36
#define GBP 136
#define GEMM_SMEM ((2 * 128 * GAP + 2 * 32 * GBP) * (int)sizeof(unsigned)) /* 71680 */

__global__ __launch_bounds__(256, 2) void gemm_f16_kernel(
    const unsigned* __restrict__ Ap, const unsigned* __restrict__ Bp,
    const float* __restrict__ bias, void* __restrict__ Cout,
    int M, int N, int K, int fp16_out)
{
    extern __shared__ unsigned smu[];
    unsigned* As = smu;                        // [2][128*36]
    unsigned* Bs = smu + 2 * 128 * GAP;        // [2][32*136]

    const int tid  = threadIdx.x;
    const int lane = tid & 31;
    const int wid  = tid >> 5;
    const int g = lane >> 2, t = lane & 3;
    const int wm = (wid & 3) * 32;
    const int wn = (wid >> 2) * 64;
    const int row0 = blockIdx.y * 128;
    const int col0 = blockIdx.x * 128;
    const int Kp = K / 2;

    float c[2][8][4] = {};
    const int NIT = K / 64;

    auto load_tile = [&](int it, int buf) {
        const int kk0 = it * 32;               // 64 k-elems = 32 uints
        unsigned* Ab = As + buf * (128 * GAP);
        unsigned* Bb = Bs + buf * (32 * GBP);
        #pragma unroll
        for (int i = 0; i < 4; i++) {          // A: 128 rows x 8 chunks
            const int ch = tid + 256 * i;
            const int r = ch >> 3, c4 = (ch & 7) * 4;
            cpa16(Ab + r * GAP + c4, Ap + (size_t)(row0 + r) * Kp + kk0 + c4);
        }
        #pragma unroll
        for (int i = 0; i < 4; i++) {          // B: 32 kk-rows x 32 chunks
            const int ch = tid + 256 * i;
            const int r = ch >> 5, c4 = (ch & 31) * 4;
            cpa16(Bb + r * GBP + c4, Bp + (size_t)(kk0 + r) * N + col0 + c4);
        }
        cp_commit();
    };

    load_tile(0, 0);
    for (int it = 0; it < NIT; it++) {
        const int buf = it & 1;
        if (it + 1 < NIT) { load_tile(it + 1, buf ^ 1); cp_wait1(); }
        else              { cp_wait0(); }
        __syncthreads();

        const unsigned* Ab = As + buf * (128 * GAP);
        const unsigned* Bb = Bs + buf * (32 * GBP);
        #pragma unroll
        for (int ks = 0; ks < 4; ks++) {       // 4 k16 steps per BK=64
            const int kb = ks * 8;
            unsigned a[2][4], b[8][2];
            #pragma unroll
            for (int mt = 0; mt < 2; mt++) {
                const int mb = wm + mt * 16;
                a[mt][0] = Ab[(mb + g    ) * GAP + kb + t    ];
                a[mt][1] = Ab[(mb + g + 8) * GAP + kb + t    ];
                a[mt][2] = Ab[(mb + g    ) * GAP + kb + t + 4];
                a[mt][3] = Ab[(mb + g + 8) * GAP + kb + t + 4];
            }
            #pragma unroll
            for (int nt = 0; nt < 8; nt++) {
                b[nt][0] = Bb[(kb + t    ) * GBP + wn + nt * 8 + g];
                b[nt][1] = Bb[(kb + t + 4) * GBP + wn + nt * 8 + g];
            }
            #pragma unroll
            for (int mt = 0; mt < 2; mt++)
                #pragma unroll
                for (int nt = 0; nt < 8; nt++)
                    mma_f16(c[mt][nt], a[mt], b[nt]);
        }
        __syncthreads();
    }

    #pragma unroll
    for (int mt = 0; mt < 2; mt++) {
        const int r = row0 + wm + mt * 16 + g;
        #pragma unroll
        for (int nt = 0; nt < 8; nt++) {
            const int cn = col0 + wn + nt * 8 + t * 2;
            const float b0 = bias[cn], b1 = bias[cn + 1];
            const float v00 = c[mt][nt][0] + b0, v01 = c[mt][nt][1] + b1;
            const float v10 = c[mt][nt][2] + b0, v11 = c[mt][nt][3] + b1;
            if (fp16_out) {
                unsigned* Cp = (unsigned*)Cout;
                Cp[(size_t)r       * (N/2) + (cn >> 1)] = pack2(v00, v01);
                Cp[(size_t)(r + 8) * (N/2) + (cn >> 1)] = pack2(v10, v11);
            } else {
                float* C = (float*)Cout;
                *(float2*)&((float*)C)[(size_t)r       * N + cn] = make_float2(v00, v01);
                *(float2*)&((float*)C)[(size_t)(r + 8) * N + cn] = make_float2(v10, v11);
            }
        }
    }
}

// ---------------------------------------------------------------------------
// Flash attention fp16: 256-row Q tile, 8 warps x 32 q-rows, k16 mma.
// K/V loaded in 128-key chunks, consumed as two 64-key passes (same buffer)
// -> half the cp.async batches and half the __syncthreads of R14, bit-exact.
//   QsPs[256][36u]  Q then P (bank 4g+t)
//   Ks[2][128][36u] key rows packed d (bank 4g+t)
//   Vs[2][64][68u]  Vt d-rows, 64 kk (=128 keys) each (bank 4g+t)
// ---------------------------------------------------------------------------
#define QT 256
#define FP 36
#define VP 68
#define FLASH_SMEM ((QT * FP + 2 * 128 * FP + 2 * 64 * VP) * (int)sizeof(unsigned)) /* 108544 */

__global__ __launch_bounds__(256) void flash_f16_kernel(
    const unsigned* __restrict__ qkvp, const unsigned* __restrict__ vtp,
    unsigned* __restrict__ attnp)
{
    extern __shared__ unsigned smu[];
    unsigned* QsPs = smu;                      // 256*36
    unsigned* Ks   = QsPs + QT * FP;           // [2][128*36]
    unsigned* Vs   = Ks + 2 * 128 * FP;        // [2][64*68]

    const int bh = blockIdx.x;
    const int b = bh / NH, h = bh % NH;
    const int q0 = blockIdx.y * QT;
    const int tid = threadIdx.x;
    const int lane = tid & 31;
    const int wid = tid >> 5;
    const int g = lane >> 2, t = lane & 3;
    const int m0 = wid * 32;

    const int QROW = QKV_N / 2;
    const unsigned* qcol = qkvp + h * 32;
    const unsigned* kcol = qkvp + HIDDEN/2 + h * 32;
    const unsigned* vtb  = vtp + (size_t)bh * HS * (SS/2);

    // Load one 128-key chunk of K + Vt.
    auto load_kv = [&](int it, int buf) {
        const int k0 = it * 128;
        unsigned* Kb = Ks + buf * (128 * FP);
        unsigned* Vb = Vs + buf * (64 * VP);
        #pragma unroll
        for (int i = 0; i < 4; i++) {          // K: 128 rows x 8 chunks
            const int ch = tid + 256 * i;      // 0..1023
            const int key = ch >> 3, c4 = (ch & 7) * 4;
            cpa16(Kb + key * FP + c4, kcol + (size_t)(b * SS + k0 + key) * QROW + c4);
        }
        #pragma unroll
        for (int i = 0; i < 4; i++) {          // Vt: 64 d-rows x 16 chunks
            const int ch = tid + 256 * i;
            const int d = ch >> 4, c4 = (ch & 15) * 4;
            cpa16(Vb + d * VP + c4, vtb + (size_t)d * (SS/2) + (k0 >> 1) + c4);
        }
        cp_commit();
    };

    load_kv(0, 0);
    const __half2 sc2 = __float2half2_rn(0.125f);
    #pragma unroll
    for (int i = 0; i < 8; i++) {
        const int e = tid + 256 * i;
        const int r = e >> 3, c4 = (e & 7) * 4;
        uint4 u = *(const uint4*)(qcol + (size_t)(b * SS + q0 + r) * QROW + c4);
        __half2 h0 = __hmul2(*(__half2*)&u.x, sc2);
        __half2 h1 = __hmul2(*(__half2*)&u.y, sc2);
        __half2 h2 = __hmul2(*(__half2*)&u.z, sc2);
        __half2 h3 = __hmul2(*(__half2*)&u.w, sc2);
        u.x = *(unsigned*)&h0; u.y = *(unsigned*)&h1;
        u.z = *(unsigned*)&h2; u.w = *(unsigned*)&h3;
        *(uint4*)(QsPs + r * FP + c4) = u;
    }
    __syncthreads();

    unsigned qf[2][4][4];
    #pragma unroll
    for (int mt = 0; mt < 2; mt++) {
        const int mb = m0 + mt * 16;
        #pragma unroll
        for (int ks = 0; ks < 4; ks++) {
            const int kb = ks * 8;
            qf[mt][ks][0] = QsPs[(mb + g    ) * FP + kb + t    ];
            qf[mt][ks][1] = QsPs[(mb + g + 8) * FP + kb + t    ];
            qf[mt][ks][2] = QsPs[(mb + g    ) * FP + kb + t + 4];
            qf[mt][ks][3] = QsPs[(mb + g + 8) * FP + kb + t + 4];
        }
    }

    float o[2][8][4] = {};
    float mrow[2][2], lrow[2][2];
    #pragma unroll
    for (int mt = 0; mt < 2; mt++) { mrow[mt][0] = mrow[mt][1] = -1e30f; lrow[mt][0] = lrow[mt][1] = 0.f; }

    const int NT = SS / 128;
    for (int it = 0; it < NT; it++) {
        const int buf = it & 1;
        if (it + 1 < NT) { load_kv(it + 1, buf ^ 1); cp_wait1(); }
        else             { cp_wait0(); }
        __syncthreads();

        const unsigned* Kb = Ks + buf * (128 * FP);
        const unsigned* Vb = Vs + buf * (64 * VP);

        // Two 64-key passes over this chunk (same order as R14's 64-key tiles).
        #pragma unroll
        for (int half = 0; half < 2; half++) {
            const unsigned* Kh = Kb + half * 64 * FP;
            const int vkb0 = half * 32;        // kk offset into Vt rows

            // ---- S = Q @ K^T ----
            float s[2][8][4] = {};
            #pragma unroll
            for (int ks = 0; ks < 4; ks++) {
                const int kb = ks * 8;
                unsigned bfr[8][2];
                #pragma unroll
                for (int nt = 0; nt < 8; nt++) {
                    bfr[nt][0] = Kh[(nt * 8 + g) * FP + kb + t    ];
                    bfr[nt][1] = Kh[(nt * 8 + g) * FP + kb + t + 4];
                }
                #pragma unroll
                for (int nt = 0; nt < 8; nt++) {
                    mma_f16(s[0][nt], qf[0][ks], bfr[nt]);
                    mma_f16(s[1][nt], qf[1][ks], bfr[nt]);
                }
            }

            // ---- online softmax + P publish ----
            #pragma unroll
            for (int mt = 0; mt < 2; mt++) {
                float mx0 = -1e30f, mx1 = -1e30f;
                #pragma unroll
                for (int nt = 0; nt < 8; nt++) {
                    mx0 = fmaxf(mx0, fmaxf(s[mt][nt][0], s[mt][nt][1]));
                    mx1 = fmaxf(mx1, fmaxf(s[mt][nt][2], s[mt][nt][3]));
                }
                mx0 = fmaxf(mx0, __shfl_xor_sync(0xffffffffu, mx0, 1));
                mx0 = fmaxf(mx0, __shfl_xor_sync(0xffffffffu, mx0, 2));
                mx1 = fmaxf(mx1, __shfl_xor_sync(0xffffffffu, mx1, 1));
                mx1 = fmaxf(mx1, __shfl_xor_sync(0xffffffffu, mx1, 2));

                const float mn0 = fmaxf(mrow[mt][0], mx0);
                const float mn1 = fmaxf(mrow[mt][1], mx1);
                const float al0 = __expf(mrow[mt][0] - mn0);
                const float al1 = __expf(mrow[mt][1] - mn1);
                mrow[mt][0] = mn0; mrow[mt][1] = mn1;

                float sum0 = 0.f, sum1 = 0.f;
                #pragma unroll
                for (int nt = 0; nt < 8; nt++) {
                    s[mt][nt][0] = __expf(s[mt][nt][0] - mn0); sum0 += s[mt][nt][0];
                    s[mt][nt][1] = __expf(s[mt][nt][1] - mn0); sum0 += s[mt][nt][1];
                    s[mt][nt][2] = __expf(s[mt][nt][2] - mn1); sum1 += s[mt][nt][2];
                    s[mt][nt][3] = __expf(s[mt][nt][3] - mn1); sum1 += s[mt][nt][3];
                }
                sum0 += __shfl_xor_sync(0xffffffffu, sum0, 1);
                sum0 += __shfl_xor_sync(0xffffffffu, sum0, 2);
                sum1 += __shfl_xor_sync(0xffffffffu, sum1, 1);
                sum1 += __shfl_xor_sync(0xffffffffu, sum1, 2);
                lrow[mt][0] = lrow[mt][0] * al0 + sum0;
                lrow[mt][1] = lrow[mt][1] * al1 + sum1;

                #pragma unroll
                for (int nt = 0; nt < 8; nt++) {
                    o[mt][nt][0] *= al0; o[mt][nt][1] *= al0;
                    o[mt][nt][2] *= al1; o[mt][nt][3] *= al1;
                }

                const int mb = m0 + mt * 16;
                #pragma unroll
                for (int nt = 0; nt < 8; nt++) {
                    QsPs[(mb + g    ) * FP + nt * 4 + t] = pack2(s[mt][nt][0], s[mt][nt][1]);
                    QsPs[(mb + g + 8) * FP + nt * 4 + t] = pack2(s[mt][nt][2], s[mt][nt][3]);
                }
            }
            __syncwarp();

            // ---- O += P @ V ----
            #pragma unroll
            for (int ks = 0; ks < 4; ks++) {
                const int kb = ks * 8;
                unsigned bfr[8][2], a0[4], a1[4];
                #pragma unroll
                for (int nt = 0; nt < 8; nt++) {
                    bfr[nt][0] = Vb[(nt * 8 + g) * VP + vkb0 + kb + t    ];
                    bfr[nt][1] = Vb[(nt * 8 + g) * VP + vkb0 + kb + t + 4];
                }
                a0[0] = QsPs[(m0 + g     ) * FP + kb + t    ];
                a0[1] = QsPs[(m0 + g +  8) * FP + kb + t    ];
                a0[2] = QsPs[(m0 + g     ) * FP + kb + t + 4];
                a0[3] = QsPs[(m0 + g +  8) * FP + kb + t + 4];
                a1[0] = QsPs[(m0 + g + 16) * FP + kb + t    ];
                a1[1] = QsPs[(m0 + g + 24) * FP + kb + t    ];
                a1[2] = QsPs[(m0 + g + 16) * FP + kb + t + 4];
                a1[3] = QsPs[(m0 + g + 24) * FP + kb + t + 4];
                #pragma unroll
                for (int nt = 0; nt < 8; nt++) {
                    mma_f16(o[0][nt], a0, bfr[nt]);
                    mma_f16(o[1][nt], a1, bfr[nt]);
                }
            }
            __syncwarp();
        }
        __syncthreads();   // all warps done with Kb/Vb before next-next chunk lands
    }

    #pragma unroll
    for (int mt = 0; mt < 2; mt++) {
        const float inv0 = 1.f / lrow[mt][0];
        const float inv1 = 1.f / lrow[mt][1];
        const int qr0 = q0 + m0 + mt * 16 + g;
        #pragma unroll
        for (int nt = 0; nt < 8; nt++) {
            const int cc = h * 32 + nt * 4 + t;
            attnp[(size_t)(b * SS + qr0    ) * (HIDDEN/2) + cc] =
                pack2(o[mt][nt][0] * inv0, o[mt][nt][1] * inv0);
            attnp[(size_t)(b * SS + qr0 + 8) * (HIDDEN/2) + cc] =
                pack2(o[mt][nt][2] * inv1, o[mt][nt][3] * inv1);
        }
    }
}

// ---------------------------------------------------------------------------
extern "C" void kernel_launch(void* const* d_in, const int* in_sizes, int n_in,
                              void* d_out, int out_size)
{
    (void)in_sizes; (void)n_in; (void)out_size;
    const float* x    = (const float*)d_in[0];
    const float* Wqkv = (const float*)d_in[1];
    const float* bqkv = (const float*)d_in[2];
    const float* Wo   = (const float*)d_in[3];
    const float* bo   = (const float*)d_in[4];
    float* out = (float*)d_out;

    unsigned *xp, *wqkvp, *wop, *qkvp, *attnp, *vtp;
    cudaGetSymbolAddress((void**)&xp, g_xp);
    cudaGetSymbolAddress((void**)&wqkvp, g_wqkvp);
    cudaGetSymbolAddress((void**)&wop, g_wop);
    cudaGetSymbolAddress((void**)&qkvp, g_qkvp);
    cudaGetSymbolAddress((void**)&attnp, g_attnp);
    cudaGetSymbolAddress((void**)&vtp, g_vtp);

    cudaFuncSetAttribute(gemm_f16_kernel,
                         cudaFuncAttributeMaxDynamicSharedMemorySize, GEMM_SMEM);
    cudaFuncSetAttribute(flash_f16_kernel,
                         cudaFuncAttributeMaxDynamicSharedMemorySize, FLASH_SMEM);

    // 0) pack inputs to fp16
    {
        const int nx = M_TOT * HIDDEN / 2;
        prep_x_kernel<<<(nx + 255) / 256, 256>>>((const float2*)x, xp, nx);
        const int nw = (HIDDEN / 2) * QKV_N;
        prep_w_kernel<<<(nw + 255) / 256, 256>>>(Wqkv, wqkvp, QKV_N, nw);
        const int no = (HIDDEN / 2) * HIDDEN;
        prep_w_kernel<<<(no + 255) / 256, 256>>>(Wo, wop, HIDDEN, no);
    }
    // 1) QKV projection -> packed fp16 qkv
    {
        dim3 grid(QKV_N / 128, M_TOT / 128);   // (24, 32)
        gemm_f16_kernel<<<grid, 256, GEMM_SMEM>>>(xp, wqkvp, bqkv, qkvp,
                                                  M_TOT, QKV_N, HIDDEN, 1);
    }
    // 1b) pack V transposed (key-pairs) for PV mma
    {
        dim3 grid(SS / 64, BB * NH);           // (32, 32)
        pack_vt_kernel<<<grid, 256>>>(qkvp, vtp);
    }
    // 2) Flash attention -> packed fp16 attn
    {
        dim3 grid(BB * NH, SS / QT);           // (32, 8)
        flash_f16_kernel<<<grid, 256, FLASH_SMEM>>>(qkvp, vtp, attnp);
    }
    // 3) Output projection -> fp32 out
    {
        dim3 grid(HIDDEN / 128, M_TOT / 128);  // (8, 32)
        gemm_f16_kernel<<<grid, 256, GEMM_SMEM>>>(attnp, wop, bo, out,
                                                  M_TOT, HIDDEN, HIDDEN, 0);
    }
}